// round 14
// baseline (speedup 1.0000x reference)
#include <cuda_runtime.h>
#include <cuda_fp16.h>
#include <stdint.h>

#define BB 32
#define SS 512
#define RR 49
#define HH 768
#define NCB 6
#define NPART 6            // 128-col partial groups for the tensor GEMM (post-reduce)
#define MROWS_T (BB*SS)    // 16384
#define NROWS_I (BB*RR)    // 1568
#define MROWS_I 1664       // padded to 13*128
#define TXB (MROWS_T/128)  // 128 text row-blocks
#define SCH 4              // S-chunks for attend
#define NB 256             // persistent back-half grid

// ================= PTX helpers =================
__device__ __forceinline__ uint32_t smem_u32(const void* p) {
    uint32_t a;
    asm("{ .reg .u64 t; cvta.to.shared.u64 t, %1; cvt.u32.u64 %0, t; }" : "=r"(a) : "l"(p));
    return a;
}
#define SMEM_SWIZZLE_128B(x) ((x) ^ (((x) >> 3) & 0x70))

__device__ __forceinline__ void cpa16(uint32_t s, const void* g) {
    asm volatile("cp.async.cg.shared.global [%0], [%1], 16;" :: "r"(s), "l"(g));
}
__device__ __forceinline__ void ldmx4(uint32_t* r, uint32_t addr) {
    asm volatile("ldmatrix.sync.aligned.m8n8.x4.shared.b16 {%0,%1,%2,%3}, [%4];"
                 : "=r"(r[0]), "=r"(r[1]), "=r"(r[2]), "=r"(r[3]) : "r"(addr));
}
__device__ __forceinline__ void mma16816(float* c, const uint32_t* a, uint32_t b0, uint32_t b1) {
    asm volatile(
        "mma.sync.aligned.m16n8k16.row.col.f32.f16.f16.f32 "
        "{%0,%1,%2,%3}, {%4,%5,%6,%7}, {%8,%9}, {%0,%1,%2,%3};"
        : "+f"(c[0]), "+f"(c[1]), "+f"(c[2]), "+f"(c[3])
        : "r"(a[0]), "r"(a[1]), "r"(a[2]), "r"(a[3]), "r"(b0), "r"(b1));
}
__device__ __forceinline__ float fast_tanh(float x) {
    const float e = __expf(2.f * x);
    return 1.f - __fdividef(2.f, e + 1.f);
}

// ================= scratch (device globals) =================
__device__ float g_ksc_part[NPART * MROWS_T];
__device__ float g_isc_part[NPART * NROWS_I];
__device__ __align__(16) float g_vft[HH];
__device__ __align__(16) float g_vfm[HH];
__device__ float g_fmc;
__device__ float g_fmsc[BB];
__device__ float g_fdot[MROWS_T];
__device__ __align__(16) float g_frout[BB * HH];
__device__ float g_wimg[BB * RR];
__device__ float g_wtxt[BB * SS];
__device__ __align__(16) float g_attI[BB * HH];
__device__ __align__(16) float g_attTp[SCH * BB * HH];
__device__ __align__(16) float g_nI[BB * HH];
__device__ __align__(16) float g_nT[BB * HH];
__device__ __align__(16) float g_mm[BB * HH];
__device__ __align__(16) __half g_tF[MROWS_T * HH];
__device__ __align__(16) __half g_iF[MROWS_I * HH];
__device__ __align__(16) __half g_w2[HH * HH];
__device__ __align__(16) __half g_w1[HH * HH];
// grid barrier state (replay-safe: g_cnt wraps to 0; g_gen compared relatively)
__device__ unsigned g_cnt = 0;
__device__ unsigned g_gen = 0;

// ================= block reduce helpers =================
__device__ __forceinline__ float bsum(float v, float* sm) {
    int tid = threadIdx.x;
    sm[tid] = v; __syncthreads();
    for (int s = blockDim.x >> 1; s > 0; s >>= 1) {
        if (tid < s) sm[tid] += sm[tid + s];
        __syncthreads();
    }
    float r = sm[0]; __syncthreads();
    return r;
}
__device__ __forceinline__ float bmax(float v, float* sm) {
    int tid = threadIdx.x;
    sm[tid] = v; __syncthreads();
    for (int s = blockDim.x >> 1; s > 0; s >>= 1) {
        if (tid < s) sm[tid] = fmaxf(sm[tid], sm[tid + s]);
        __syncthreads();
    }
    float r = sm[0]; __syncthreads();
    return r;
}

// ================= generational grid barrier =================
__device__ __forceinline__ void grid_bar() {
    __threadfence();
    __syncthreads();
    if (threadIdx.x == 0) {
        unsigned gen = atomicAdd(&g_gen, 0u);          // read BEFORE arriving
        if (atomicInc(&g_cnt, NB - 1u) == NB - 1u) {
            atomicAdd(&g_gen, 1u);                      // release
        } else {
            while (atomicAdd(&g_gen, 0u) == gen) __nanosleep(64);
        }
    }
    __syncthreads();
    __threadfence();
}

// ================= prep: rank-1 collapses =================
__global__ void prep_kernel(const float* __restrict__ ftw, const float* __restrict__ fmw,
                            const float* __restrict__ fmb, const float* __restrict__ fgw) {
    __shared__ float red[128];
    const int k = blockIdx.x, tid = threadIdx.x;
    float s1 = 0.f, s2 = 0.f, s3 = 0.f;
    for (int h = tid; h < HH; h += 128) {
        float g1 = fgw[h], g2 = fgw[HH + h];
        s1 += ftw[k * HH + h] * g1;
        s2 += fmw[k * HH + h] * g2;
        if (k == 0) s3 += fmb[h] * g2;
    }
    float t1 = bsum(s1, red);
    float t2 = bsum(s2, red);
    if (tid == 0) { g_vft[k] = t1; g_vfm[k] = t2; }
    if (k == 0) {
        float t3 = bsum(s3, red);
        if (tid == 0) g_fmc = t3;
    }
}

// ================= cvt_prep: conversions + fgate dot + weight transpose ============
__global__ __launch_bounds__(256)
void cvt_prep(const float* __restrict__ text, const float* __restrict__ img,
              const float* __restrict__ t2w, const float* __restrict__ i1w) {
    const int bx = blockIdx.x, tid = threadIdx.x;
    if (bx < 2048) {
        const int warp = tid >> 5, lane = tid & 31;
        const int row = bx * 8 + warp;
        const float4* tv = (const float4*)(text + (size_t)row * HH);
        uint2* tout = (uint2*)(g_tF + (size_t)row * HH);
        const float4* vv = (const float4*)g_vft;
        float p = 0.f;
#pragma unroll
        for (int i = 0; i < 6; i++) {
            float4 v = tv[lane + i * 32];
            float4 f = vv[lane + i * 32];
            p += v.x * f.x + v.y * f.y + v.z * f.z + v.w * f.w;
            union { __half h[4]; uint2 u; } H;
            H.h[0] = __float2half(v.x); H.h[1] = __float2half(v.y);
            H.h[2] = __float2half(v.z); H.h[3] = __float2half(v.w);
            tout[lane + i * 32] = H.u;
        }
#pragma unroll
        for (int off = 16; off > 0; off >>= 1) p += __shfl_xor_sync(0xffffffffu, p, off);
        if (lane == 0) g_fdot[row] = p;
    } else if (bx < 2244) {
        const int warp = tid >> 5, lane = tid & 31;
        const int row = (bx - 2048) * 8 + warp;
        const float4* iv = (const float4*)(img + (size_t)row * HH);
        uint2* iout = (uint2*)(g_iF + (size_t)row * HH);
#pragma unroll
        for (int i = 0; i < 6; i++) {
            float4 v = iv[lane + i * 32];
            union { __half h[4]; uint2 u; } H;
            H.h[0] = __float2half(v.x); H.h[1] = __float2half(v.y);
            H.h[2] = __float2half(v.z); H.h[3] = __float2half(v.w);
            iout[lane + i * 32] = H.u;
        }
    } else {
        __shared__ float t[32][33];
        const int tt0 = bx - 2244;
        const int z = tt0 >= 576;
        const int tt = z ? tt0 - 576 : tt0;
        const float* W = z ? i1w : t2w;
        __half* Hi = z ? g_w1 : g_w2;
        const int kb = (tt / 24) * 32, nb = (tt % 24) * 32;
        const int tx = tid & 31, ty = tid >> 5;
#pragma unroll
        for (int i = 0; i < 4; ++i)
            t[ty + 8 * i][tx] = W[(size_t)(kb + ty + 8 * i) * HH + nb + tx];
        __syncthreads();
#pragma unroll
        for (int i = 0; i < 4; ++i)
            Hi[(size_t)(nb + ty + 8 * i) * HH + kb + tx] = __float2half(t[tx][ty + 8 * i]);
    }
}

// ================= single-pass fp16 HMMA GEMM + tanh + dot epilogue =================
#define HMMA_SMEM (96 * 1024)

__device__ __forceinline__ void issue_chunk(
    const __half* __restrict__ Ap, const __half* __restrict__ Bp,
    int kt, uint32_t stageBase, int tid, int rowBase, int colBase) {
#pragma unroll
    for (int i = 0; i < 4; i++) {
        int u = tid + i * 256;
        cpa16(stageBase + SMEM_SWIZZLE_128B((uint32_t)u * 16u),
              Ap + (size_t)(rowBase + (u >> 3)) * HH + kt + (u & 7) * 8);
    }
#pragma unroll
    for (int i = 0; i < 4; i++) {
        int u = tid + i * 256;
        cpa16(stageBase + 16384u + SMEM_SWIZZLE_128B((uint32_t)u * 16u),
              Bp + (size_t)(colBase + (u >> 3)) * HH + kt + (u & 7) * 8);
    }
    asm volatile("cp.async.commit_group;");
}

__global__ __launch_bounds__(256, 2)
void hmma_tanh_dot(const __half* __restrict__ AT, const __half* __restrict__ AI,
                   const __half* __restrict__ WT, const __half* __restrict__ WI,
                   const float* __restrict__ avT, const float* __restrict__ avI,
                   float* __restrict__ outT, float* __restrict__ outI) {
    extern __shared__ __align__(1024) char smem[];
    const uint32_t sb = smem_u32(smem);
    const int tid = threadIdx.x;
    const int wid = tid >> 5, lane = tid & 31;
    const int warpm = wid & 1, warpn = wid >> 1;
    const int bx = blockIdx.x;
    const bool isT = bx < TXB;
    const __half* A = isT ? AT : AI;
    const __half* W = isT ? WT : WI;
    const float* av = isT ? avT : avI;
    float* outPart = isT ? outT : outI;
    const int nrows = isT ? MROWS_T : NROWS_I;
    const int rowBase = (isT ? bx : bx - TXB) * 128;
    const int colBase = blockIdx.y * 128;

    float acc[4][4][4];
#pragma unroll
    for (int i = 0; i < 4; i++)
#pragma unroll
        for (int j = 0; j < 4; j++)
#pragma unroll
            for (int q = 0; q < 4; q++) acc[i][j][q] = 0.f;

    issue_chunk(A, W, 0, sb, tid, rowBase, colBase);
    issue_chunk(A, W, 64, sb + 32768u, tid, rowBase, colBase);

    for (int it = 0; it < 12; ++it) {
        if (it < 11) asm volatile("cp.async.wait_group 1;");
        else         asm volatile("cp.async.wait_group 0;");
        __syncthreads();
        if (it < 10)
            issue_chunk(A, W, (it + 2) * 64, sb + (uint32_t)((it + 2) % 3) * 32768u,
                        tid, rowBase, colBase);

        const uint32_t abase = sb + (uint32_t)(it % 3) * 32768u;
        const uint32_t bbase = abase + 16384u;
#pragma unroll
        for (int ks = 0; ks < 4; ++ks) {
            uint32_t bf[2][4];
#pragma unroll
            for (int g = 0; g < 2; ++g) {
                const int n = warpn * 32 + g * 16 + (lane & 7) + ((lane >> 4) << 3);
                const int kb = ks * 32 + ((lane >> 3) & 1) * 16;
                ldmx4(bf[g], bbase + SMEM_SWIZZLE_128B((uint32_t)(n * 128 + kb)));
            }
#pragma unroll
            for (int mt = 0; mt < 4; ++mt) {
                uint32_t a[4];
                const int r = warpm * 64 + mt * 16 + (lane & 15);
                const int kb = ks * 32 + ((lane >> 4) << 4);
                ldmx4(a, abase + SMEM_SWIZZLE_128B((uint32_t)(r * 128 + kb)));
#pragma unroll
                for (int nt = 0; nt < 4; ++nt)
                    mma16816(acc[mt][nt], a, bf[nt >> 1][(nt & 1) * 2],
                             bf[nt >> 1][(nt & 1) * 2 + 1]);
            }
        }
    }

    const float* avp = av + colBase + warpn * 32;
    float avv[4][2];
#pragma unroll
    for (int nt = 0; nt < 4; ++nt) {
        avv[nt][0] = avp[nt * 8 + (lane & 3) * 2];
        avv[nt][1] = avp[nt * 8 + (lane & 3) * 2 + 1];
    }
    float sarr[4][2];
#pragma unroll
    for (int mt = 0; mt < 4; ++mt) {
        float s0 = 0.f, s1 = 0.f;
#pragma unroll
        for (int nt = 0; nt < 4; ++nt) {
            s0 += fast_tanh(acc[mt][nt][0]) * avv[nt][0] + fast_tanh(acc[mt][nt][1]) * avv[nt][1];
            s1 += fast_tanh(acc[mt][nt][2]) * avv[nt][0] + fast_tanh(acc[mt][nt][3]) * avv[nt][1];
        }
        s0 += __shfl_xor_sync(0xffffffffu, s0, 1);
        s0 += __shfl_xor_sync(0xffffffffu, s0, 2);
        s1 += __shfl_xor_sync(0xffffffffu, s1, 1);
        s1 += __shfl_xor_sync(0xffffffffu, s1, 2);
        sarr[mt][0] = s0; sarr[mt][1] = s1;
    }
    __syncthreads();
    float* rs = (float*)smem;
    if ((lane & 3) == 0) {
#pragma unroll
        for (int mt = 0; mt < 4; ++mt) {
            rs[wid * 64 + mt * 16 + (lane >> 2)] = sarr[mt][0];
            rs[wid * 64 + mt * 16 + 8 + (lane >> 2)] = sarr[mt][1];
        }
    }
    __syncthreads();
    if (wid < 4) {
        const int rl = wid * 32 + lane;
        const int wm = rl >> 6, idx = rl & 63;
        float sum = rs[(wm + 0) * 64 + idx] + rs[(wm + 2) * 64 + idx]
                  + rs[(wm + 4) * 64 + idx] + rs[(wm + 6) * 64 + idx];
        const int r = rowBase + rl;
        if (r < nrows) outPart[blockIdx.y * nrows + r] = sum;
    }
}

// ================= persistent back-half: softmax->attend->nit->gate->fr->out =======
__global__ __launch_bounds__(256)
void backhalf(const float* __restrict__ img,
              const float* __restrict__ giw, const float* __restrict__ gib,
              const float* __restrict__ gtw, const float* __restrict__ gtb,
              const float* __restrict__ ggw, const float* __restrict__ ggb,
              const float* __restrict__ fgb,
              const float* __restrict__ frw, const float* __restrict__ frb,
              float* __restrict__ out) {
    __shared__ __align__(16) float SM[5248];   // max of phase layouts (~21 KB)
    const int cta = blockIdx.x, tid = threadIdx.x;
    const int wid = tid >> 5, lane = tid & 31;

    // ---- Phase A: softmaxes (cta < 32) ----
    if (cta < BB) {
        const int b = cta;
        float* red = SM;
        float vs = 0.f, s0 = -1e30f;
        if (tid < RR) {
#pragma unroll
            for (int c = 0; c < NPART; c++) vs += g_isc_part[c * NROWS_I + b * RR + tid];
            s0 = vs;
        }
        float mx = bmax(s0, red);
        float ex = (tid < RR) ? expf(vs - mx) : 0.f;
        float tot = bsum(ex, red);
        if (tid < RR) g_wimg[b * RR + tid] = ex / tot;

        float sa = 0.f, sb2 = 0.f;
#pragma unroll
        for (int c = 0; c < NPART; c++) {
            sa  += g_ksc_part[c * MROWS_T + b * SS + tid];
            sb2 += g_ksc_part[c * MROWS_T + b * SS + tid + 256];
        }
        float mx2 = bmax(fmaxf(sa, sb2), red);
        float ea = expf(sa - mx2), eb = expf(sb2 - mx2);
        float tot2 = bsum(ea + eb, red);
        g_wtxt[b * SS + tid] = ea / tot2;
        g_wtxt[b * SS + tid + 256] = eb / tot2;
    }
    grid_bar();

    // ---- Phase B: attend partials (cta < 128): unit (b, sch) ----
    if (cta < BB * SCH) {
        const int b = cta >> 2, sch = cta & 3;
        const int j0 = sch * 128;
        float* wt = SM;
        float* wi = SM + 128;
        if (tid < 128) wt[tid] = g_wtxt[b * SS + j0 + tid];
        if (sch == 0 && tid >= 128 && tid < 128 + RR) wi[tid - 128] = g_wimg[b * RR + tid - 128];
        __syncthreads();
        for (int c = tid; c < HH / 2; c += 256) {
            const __half2* tp = (const __half2*)g_tF + (size_t)(b * SS + j0) * (HH / 2) + c;
            float2 a = {0.f, 0.f};
#pragma unroll 8
            for (int j = 0; j < 128; ++j) {
                float2 v = __half22float2(tp[(size_t)j * (HH / 2)]);
                a.x += wt[j] * v.x; a.y += wt[j] * v.y;
            }
            ((float2*)(g_attTp + ((size_t)sch * BB + b) * HH))[c] = a;
            if (sch == 0) {
                const float2* ip = (const float2*)(img + (size_t)b * RR * HH) + c;
                float2 ai = {0.f, 0.f};
#pragma unroll
                for (int r = 0; r < RR; ++r) {
                    float2 v = ip[(size_t)r * (HH / 2)];
                    ai.x += wi[r] * v.x; ai.y += wi[r] * v.y;
                }
                ((float2*)(g_attI + b * HH))[c] = ai;
            }
        }
    }
    grid_bar();

    // ---- Phase C: nI/nT small GEMMs (cta < 12): unit (colblk, isT) ----
    if (cta < 2 * NCB) {
        const bool isT = cta >= NCB;
        const int colBase = (cta % NCB) * 128;
        const float* W = isT ? gtw : giw;
        const float* bias = isT ? gtb : gib;
        float* C = isT ? g_nT : g_nI;
        float (*As)[36] = (float(*)[36])SM;             // 32x36
        float (*Ws)[128] = (float(*)[128])(SM + 1152);  // 32x128
        const int tx = tid & 31, ty = tid >> 5;

        float acc[4][4];
#pragma unroll
        for (int i = 0; i < 4; i++)
#pragma unroll
            for (int j = 0; j < 4; j++) acc[i][j] = 0.f;

        for (int kt = 0; kt < HH; kt += 32) {
            {
                int r = tid >> 3;
                int kg = (tid & 7) << 2;
                float4 v;
                if (isT) {
                    v = *(const float4*)(g_attTp + (size_t)r * HH + kt + kg);
#pragma unroll
                    for (int s = 1; s < SCH; ++s) {
                        float4 p = *(const float4*)(g_attTp + ((size_t)s * BB + r) * HH + kt + kg);
                        v.x += p.x; v.y += p.y; v.z += p.z; v.w += p.w;
                    }
                } else {
                    v = *(const float4*)(g_attI + (size_t)r * HH + kt + kg);
                }
                As[kg + 0][r] = v.x; As[kg + 1][r] = v.y;
                As[kg + 2][r] = v.z; As[kg + 3][r] = v.w;
            }
#pragma unroll
            for (int i = 0; i < 4; i++) {
                int idx = tid + i * 256;
                int kk = idx >> 5;
                int ng = (idx & 31) << 2;
                *(float4*)&Ws[kk][ng] = *(const float4*)(W + (kt + kk) * HH + colBase + ng);
            }
            __syncthreads();
#pragma unroll
            for (int k = 0; k < 32; k++) {
                float4 av4 = *(const float4*)&As[k][ty * 4];
                float4 w = *(const float4*)&Ws[k][tx * 4];
                float a[4] = {av4.x, av4.y, av4.z, av4.w};
#pragma unroll
                for (int i = 0; i < 4; i++) {
                    acc[i][0] = fmaf(a[i], w.x, acc[i][0]);
                    acc[i][1] = fmaf(a[i], w.y, acc[i][1]);
                    acc[i][2] = fmaf(a[i], w.z, acc[i][2]);
                    acc[i][3] = fmaf(a[i], w.w, acc[i][3]);
                }
            }
            __syncthreads();
        }
        int col = colBase + tx * 4;
        float4 bv = *(const float4*)(bias + col);
#pragma unroll
        for (int i = 0; i < 4; i++) {
            int row = ty * 4 + i;
            float4 o;
            o.x = tanhf(acc[i][0] + bv.x);
            o.y = tanhf(acc[i][1] + bv.y);
            o.z = tanhf(acc[i][2] + bv.z);
            o.w = tanhf(acc[i][3] + bv.w);
            *(float4*)(C + row * HH + col) = o;
        }
    }
    grid_bar();

    // ---- Phase D: gate + multimodal + fm score (cta < 32) ----
    if (cta < BB) {
        const int b = cta;
        float* red = SM;
        float gp = 0.f;
        for (int h = tid; h < HH; h += 256)
            gp += g_nI[b * HH + h] * ggw[h] + g_nT[b * HH + h] * ggw[HH + h];
        float gs = bsum(gp, red);
        float gate = 1.f / (1.f + expf(-(gs + ggb[0])));

        float fmp = 0.f;
        for (int h = tid; h < HH; h += 256) {
            float v = gate * g_nI[b * HH + h] + (1.f - gate) * g_nT[b * HH + h];
            g_mm[b * HH + h] = v;
            fmp += v * g_vfm[h];
        }
        float fsum = bsum(fmp, red);
        if (tid == 0) g_fmsc[b] = fsum + g_fmc + fgb[0];
    }
    grid_bar();

    // ---- Phase E: fr GEMM (cta < 6) ----
    if (cta < NCB) {
        const int colBase = cta * 128;
        float (*As)[36] = (float(*)[36])SM;
        float (*Ws)[128] = (float(*)[128])(SM + 1152);
        const int tx = tid & 31, ty = tid >> 5;

        float acc[4][4];
#pragma unroll
        for (int i = 0; i < 4; i++)
#pragma unroll
            for (int j = 0; j < 4; j++) acc[i][j] = 0.f;

        for (int kt = 0; kt < HH; kt += 32) {
            {
                int r = tid >> 3;
                int kg = (tid & 7) << 2;
                float4 v = *(const float4*)(g_mm + (size_t)r * HH + kt + kg);
                As[kg + 0][r] = v.x; As[kg + 1][r] = v.y;
                As[kg + 2][r] = v.z; As[kg + 3][r] = v.w;
            }
#pragma unroll
            for (int i = 0; i < 4; i++) {
                int idx = tid + i * 256;
                int kk = idx >> 5;
                int ng = (idx & 31) << 2;
                *(float4*)&Ws[kk][ng] = *(const float4*)(frw + (kt + kk) * HH + colBase + ng);
            }
            __syncthreads();
#pragma unroll
            for (int k = 0; k < 32; k++) {
                float4 av4 = *(const float4*)&As[k][ty * 4];
                float4 w = *(const float4*)&Ws[k][tx * 4];
                float a[4] = {av4.x, av4.y, av4.z, av4.w};
#pragma unroll
                for (int i = 0; i < 4; i++) {
                    acc[i][0] = fmaf(a[i], w.x, acc[i][0]);
                    acc[i][1] = fmaf(a[i], w.y, acc[i][1]);
                    acc[i][2] = fmaf(a[i], w.z, acc[i][2]);
                    acc[i][3] = fmaf(a[i], w.w, acc[i][3]);
                }
            }
            __syncthreads();
        }
        int col = colBase + tx * 4;
        float4 bv = *(const float4*)(frb + col);
#pragma unroll
        for (int i = 0; i < 4; i++) {
            int row = ty * 4 + i;
            float4 o;
            o.x = tanhf(acc[i][0] + bv.x);
            o.y = tanhf(acc[i][1] + bv.y);
            o.z = tanhf(acc[i][2] + bv.z);
            o.w = tanhf(acc[i][3] + bv.w);
            *(float4*)(g_frout + row * HH + col) = o;
        }
    }
    grid_bar();

    // ---- Phase F: output (all CTAs, warp per row, strided) ----
    {
        const int gw0 = cta * 8 + wid;           // global warp id
        for (int row = gw0; row < MROWS_T; row += NB * 8) {
            const int b = row >> 9;
            const float fg = 1.f / (1.f + expf(-(g_fdot[row] + g_fmsc[b])));
            const float4* fr = (const float4*)(g_frout + b * HH);
            float4* op = (float4*)(out + (size_t)row * HH);
#pragma unroll
            for (int i = 0; i < 6; i++) {
                float4 f = fr[lane + i * 32];
                float4 o;
                o.x = fg * f.x; o.y = fg * f.y; o.z = fg * f.z; o.w = fg * f.w;
                op[lane + i * 32] = o;
            }
        }
    }
}

// ================= launch =================
extern "C" void kernel_launch(void* const* d_in, const int* in_sizes, int n_in,
                              void* d_out, int out_size) {
    const float* text = (const float*)d_in[0];
    const float* img  = (const float*)d_in[1];
    const float* i1w  = (const float*)d_in[4];
    const float* a1w  = (const float*)d_in[5];
    const float* t2w  = (const float*)d_in[7];
    const float* a2w  = (const float*)d_in[10];
    const float* gtw  = (const float*)d_in[12];
    const float* gtb  = (const float*)d_in[13];
    const float* giw  = (const float*)d_in[14];
    const float* gib  = (const float*)d_in[15];
    const float* ggw  = (const float*)d_in[16];
    const float* ggb  = (const float*)d_in[17];
    const float* ftw  = (const float*)d_in[18];
    const float* fmw  = (const float*)d_in[19];
    const float* fmb  = (const float*)d_in[20];
    const float* fgw  = (const float*)d_in[21];
    const float* fgb  = (const float*)d_in[22];
    const float* frw  = (const float*)d_in[23];
    const float* frb  = (const float*)d_in[24];
    float* out = (float*)d_out;

    float* kscp;  cudaGetSymbolAddress((void**)&kscp,  g_ksc_part);
    float* iscp;  cudaGetSymbolAddress((void**)&iscp,  g_isc_part);
    __half *tF, *iF, *w2, *w1;
    cudaGetSymbolAddress((void**)&tF, g_tF);
    cudaGetSymbolAddress((void**)&iF, g_iF);
    cudaGetSymbolAddress((void**)&w2, g_w2);
    cudaGetSymbolAddress((void**)&w1, g_w1);

    cudaFuncSetAttribute(hmma_tanh_dot, cudaFuncAttributeMaxDynamicSharedMemorySize, HMMA_SMEM);

    // 1. rank-1 collapses (v_ft needed by cvt_prep text part)
    prep_kernel<<<HH, 128>>>(ftw, fmw, fmb, fgw);

    // 2. fp16 conversions + fgate dot + weight transposes
    cvt_prep<<<2244 + 1152, 256>>>(text, img, t2w, i1w);

    // 3. merged text + img GEMM partials
    {
        dim3 g(TXB + MROWS_I / 128, HH / 128);
        hmma_tanh_dot<<<g, 256, HMMA_SMEM>>>(tF, iF, w2, w1, a2w + HH, a1w + HH, kscp, iscp);
    }

    // 4. persistent back-half
    backhalf<<<NB, 256>>>(img, giw, gib, gtw, gtb, ggw, ggb, fgb, frw, frb, out);
}

// round 15
// speedup vs baseline: 1.0103x; 1.0103x over previous
#include <cuda_runtime.h>
#include <cuda_fp16.h>
#include <stdint.h>

#define BB 32
#define SS 512
#define RR 49
#define HH 768
#define NCB 6
#define NPART 6            // 128-col partial groups for the tensor GEMM (post-reduce)
#define MROWS_T (BB*SS)    // 16384
#define NROWS_I (BB*RR)    // 1568
#define MROWS_I 1664       // padded to 13*128
#define TXB (MROWS_T/128)  // 128 text row-blocks
#define SCH 4              // S-chunks for attend

// ================= PTX helpers =================
__device__ __forceinline__ uint32_t smem_u32(const void* p) {
    uint32_t a;
    asm("{ .reg .u64 t; cvta.to.shared.u64 t, %1; cvt.u32.u64 %0, t; }" : "=r"(a) : "l"(p));
    return a;
}
#define SMEM_SWIZZLE_128B(x) ((x) ^ (((x) >> 3) & 0x70))

__device__ __forceinline__ void cpa16(uint32_t s, const void* g) {
    asm volatile("cp.async.cg.shared.global [%0], [%1], 16;" :: "r"(s), "l"(g));
}
__device__ __forceinline__ void ldmx4(uint32_t* r, uint32_t addr) {
    asm volatile("ldmatrix.sync.aligned.m8n8.x4.shared.b16 {%0,%1,%2,%3}, [%4];"
                 : "=r"(r[0]), "=r"(r[1]), "=r"(r[2]), "=r"(r[3]) : "r"(addr));
}
__device__ __forceinline__ void mma16816(float* c, const uint32_t* a, uint32_t b0, uint32_t b1) {
    asm volatile(
        "mma.sync.aligned.m16n8k16.row.col.f32.f16.f16.f32 "
        "{%0,%1,%2,%3}, {%4,%5,%6,%7}, {%8,%9}, {%0,%1,%2,%3};"
        : "+f"(c[0]), "+f"(c[1]), "+f"(c[2]), "+f"(c[3])
        : "r"(a[0]), "r"(a[1]), "r"(a[2]), "r"(a[3]), "r"(b0), "r"(b1));
}
__device__ __forceinline__ float fast_tanh(float x) {
    const float e = __expf(2.f * x);
    return 1.f - __fdividef(2.f, e + 1.f);
}

// ================= scratch (device globals) =================
__device__ float g_ksc_part[NPART * MROWS_T];
__device__ float g_isc_part[NPART * NROWS_I];
__device__ __align__(16) float g_vft[HH];
__device__ __align__(16) float g_vfm[HH];
__device__ float g_fmc;
__device__ float g_fmsc[BB];
__device__ float g_fdot[MROWS_T];
__device__ __align__(16) float g_frout[BB * HH];
__device__ float g_wimg[BB * RR];
__device__ float g_wtxt[BB * SS];
__device__ __align__(16) float g_attI[BB * HH];
__device__ __align__(16) float g_attTp[SCH * BB * HH];   // att_text partials per S-chunk
__device__ __align__(16) float g_nI[BB * HH];
__device__ __align__(16) float g_nT[BB * HH];
// fp16 inputs + weights (transposed [n][k])
__device__ __align__(16) __half g_tF[MROWS_T * HH];
__device__ __align__(16) __half g_iF[MROWS_I * HH];   // pad rows stay zero
__device__ __align__(16) __half g_w2[HH * HH];
__device__ __align__(16) __half g_w1[HH * HH];

// ================= block reduce helpers =================
__device__ __forceinline__ float bsum(float v, float* sm) {
    int tid = threadIdx.x;
    sm[tid] = v; __syncthreads();
    for (int s = blockDim.x >> 1; s > 0; s >>= 1) {
        if (tid < s) sm[tid] += sm[tid + s];
        __syncthreads();
    }
    float r = sm[0]; __syncthreads();
    return r;
}
__device__ __forceinline__ float bmax(float v, float* sm) {
    int tid = threadIdx.x;
    sm[tid] = v; __syncthreads();
    for (int s = blockDim.x >> 1; s > 0; s >>= 1) {
        if (tid < s) sm[tid] = fmaxf(sm[tid], sm[tid + s]);
        __syncthreads();
    }
    float r = sm[0]; __syncthreads();
    return r;
}

// ================= prep: rank-1 collapses =================
__global__ void prep_kernel(const float* __restrict__ ftw, const float* __restrict__ fmw,
                            const float* __restrict__ fmb, const float* __restrict__ fgw) {
    __shared__ float red[128];
    const int k = blockIdx.x, tid = threadIdx.x;
    float s1 = 0.f, s2 = 0.f, s3 = 0.f;
    for (int h = tid; h < HH; h += 128) {
        float g1 = fgw[h], g2 = fgw[HH + h];
        s1 += ftw[k * HH + h] * g1;
        s2 += fmw[k * HH + h] * g2;
        if (k == 0) s3 += fmb[h] * g2;
    }
    float t1 = bsum(s1, red);
    float t2 = bsum(s2, red);
    if (tid == 0) { g_vft[k] = t1; g_vfm[k] = t2; }
    if (k == 0) {
        float t3 = bsum(s3, red);
        if (tid == 0) g_fmc = t3;
    }
}

// ================= cvt_prep: conversions + fgate dot + weight transpose ============
__global__ __launch_bounds__(256)
void cvt_prep(const float* __restrict__ text, const float* __restrict__ img,
              const float* __restrict__ t2w, const float* __restrict__ i1w) {
    const int bx = blockIdx.x, tid = threadIdx.x;
    if (bx < 2048) {
        const int warp = tid >> 5, lane = tid & 31;
        const int row = bx * 8 + warp;
        const float4* tv = (const float4*)(text + (size_t)row * HH);
        uint2* tout = (uint2*)(g_tF + (size_t)row * HH);
        const float4* vv = (const float4*)g_vft;
        float p = 0.f;
#pragma unroll
        for (int i = 0; i < 6; i++) {
            float4 v = tv[lane + i * 32];
            float4 f = vv[lane + i * 32];
            p += v.x * f.x + v.y * f.y + v.z * f.z + v.w * f.w;
            union { __half h[4]; uint2 u; } H;
            H.h[0] = __float2half(v.x); H.h[1] = __float2half(v.y);
            H.h[2] = __float2half(v.z); H.h[3] = __float2half(v.w);
            tout[lane + i * 32] = H.u;
        }
#pragma unroll
        for (int off = 16; off > 0; off >>= 1) p += __shfl_xor_sync(0xffffffffu, p, off);
        if (lane == 0) g_fdot[row] = p;
    } else if (bx < 2244) {
        const int warp = tid >> 5, lane = tid & 31;
        const int row = (bx - 2048) * 8 + warp;     // 0..1567
        const float4* iv = (const float4*)(img + (size_t)row * HH);
        uint2* iout = (uint2*)(g_iF + (size_t)row * HH);
#pragma unroll
        for (int i = 0; i < 6; i++) {
            float4 v = iv[lane + i * 32];
            union { __half h[4]; uint2 u; } H;
            H.h[0] = __float2half(v.x); H.h[1] = __float2half(v.y);
            H.h[2] = __float2half(v.z); H.h[3] = __float2half(v.w);
            iout[lane + i * 32] = H.u;
        }
    } else {
        __shared__ float t[32][33];
        const int tt0 = bx - 2244;
        const int z = tt0 >= 576;
        const int tt = z ? tt0 - 576 : tt0;
        const float* W = z ? i1w : t2w;
        __half* Hi = z ? g_w1 : g_w2;
        const int kb = (tt / 24) * 32, nb = (tt % 24) * 32;
        const int tx = tid & 31, ty = tid >> 5;
#pragma unroll
        for (int i = 0; i < 4; ++i)
            t[ty + 8 * i][tx] = W[(size_t)(kb + ty + 8 * i) * HH + nb + tx];
        __syncthreads();
#pragma unroll
        for (int i = 0; i < 4; ++i)
            Hi[(size_t)(nb + ty + 8 * i) * HH + kb + tx] = __float2half(t[tx][ty + 8 * i]);
    }
}

// ================= single-pass fp16 HMMA GEMM + tanh + dot epilogue =================
#define HMMA_SMEM (96 * 1024)

__device__ __forceinline__ void issue_chunk(
    const __half* __restrict__ Ap, const __half* __restrict__ Bp,
    int kt, uint32_t stageBase, int tid, int rowBase, int colBase) {
#pragma unroll
    for (int i = 0; i < 4; i++) {
        int u = tid + i * 256;
        cpa16(stageBase + SMEM_SWIZZLE_128B((uint32_t)u * 16u),
              Ap + (size_t)(rowBase + (u >> 3)) * HH + kt + (u & 7) * 8);
    }
#pragma unroll
    for (int i = 0; i < 4; i++) {
        int u = tid + i * 256;
        cpa16(stageBase + 16384u + SMEM_SWIZZLE_128B((uint32_t)u * 16u),
              Bp + (size_t)(colBase + (u >> 3)) * HH + kt + (u & 7) * 8);
    }
    asm volatile("cp.async.commit_group;");
}

__global__ __launch_bounds__(256, 2)
void hmma_tanh_dot(const __half* __restrict__ AT, const __half* __restrict__ AI,
                   const __half* __restrict__ WT, const __half* __restrict__ WI,
                   const float* __restrict__ avT, const float* __restrict__ avI,
                   float* __restrict__ outT, float* __restrict__ outI) {
    extern __shared__ __align__(1024) char smem[];
    const uint32_t sb = smem_u32(smem);
    const int tid = threadIdx.x;
    const int wid = tid >> 5, lane = tid & 31;
    const int warpm = wid & 1, warpn = wid >> 1;
    const int bx = blockIdx.x;
    const bool isT = bx < TXB;
    const __half* A = isT ? AT : AI;
    const __half* W = isT ? WT : WI;
    const float* av = isT ? avT : avI;
    float* outPart = isT ? outT : outI;
    const int nrows = isT ? MROWS_T : NROWS_I;
    const int rowBase = (isT ? bx : bx - TXB) * 128;
    const int colBase = blockIdx.y * 128;

    float acc[4][4][4];
#pragma unroll
    for (int i = 0; i < 4; i++)
#pragma unroll
        for (int j = 0; j < 4; j++)
#pragma unroll
            for (int q = 0; q < 4; q++) acc[i][j][q] = 0.f;

    issue_chunk(A, W, 0, sb, tid, rowBase, colBase);
    issue_chunk(A, W, 64, sb + 32768u, tid, rowBase, colBase);

    for (int it = 0; it < 12; ++it) {
        if (it < 11) asm volatile("cp.async.wait_group 1;");
        else         asm volatile("cp.async.wait_group 0;");
        __syncthreads();
        if (it < 10)
            issue_chunk(A, W, (it + 2) * 64, sb + (uint32_t)((it + 2) % 3) * 32768u,
                        tid, rowBase, colBase);

        const uint32_t abase = sb + (uint32_t)(it % 3) * 32768u;
        const uint32_t bbase = abase + 16384u;
#pragma unroll
        for (int ks = 0; ks < 4; ++ks) {
            uint32_t bf[2][4];
#pragma unroll
            for (int g = 0; g < 2; ++g) {
                const int n = warpn * 32 + g * 16 + (lane & 7) + ((lane >> 4) << 3);
                const int kb = ks * 32 + ((lane >> 3) & 1) * 16;
                ldmx4(bf[g], bbase + SMEM_SWIZZLE_128B((uint32_t)(n * 128 + kb)));
            }
#pragma unroll
            for (int mt = 0; mt < 4; ++mt) {
                uint32_t a[4];
                const int r = warpm * 64 + mt * 16 + (lane & 15);
                const int kb = ks * 32 + ((lane >> 4) << 4);
                ldmx4(a, abase + SMEM_SWIZZLE_128B((uint32_t)(r * 128 + kb)));
#pragma unroll
                for (int nt = 0; nt < 4; ++nt)
                    mma16816(acc[mt][nt], a, bf[nt >> 1][(nt & 1) * 2],
                             bf[nt >> 1][(nt & 1) * 2 + 1]);
            }
        }
    }

    // ---- epilogue: tanh * av per warp, then cross-warpn reduction via smem ----
    const float* avp = av + colBase + warpn * 32;
    float avv[4][2];
#pragma unroll
    for (int nt = 0; nt < 4; ++nt) {
        avv[nt][0] = avp[nt * 8 + (lane & 3) * 2];
        avv[nt][1] = avp[nt * 8 + (lane & 3) * 2 + 1];
    }
    float sarr[4][2];
#pragma unroll
    for (int mt = 0; mt < 4; ++mt) {
        float s0 = 0.f, s1 = 0.f;
#pragma unroll
        for (int nt = 0; nt < 4; ++nt) {
            s0 += fast_tanh(acc[mt][nt][0]) * avv[nt][0] + fast_tanh(acc[mt][nt][1]) * avv[nt][1];
            s1 += fast_tanh(acc[mt][nt][2]) * avv[nt][0] + fast_tanh(acc[mt][nt][3]) * avv[nt][1];
        }
        s0 += __shfl_xor_sync(0xffffffffu, s0, 1);
        s0 += __shfl_xor_sync(0xffffffffu, s0, 2);
        s1 += __shfl_xor_sync(0xffffffffu, s1, 1);
        s1 += __shfl_xor_sync(0xffffffffu, s1, 2);
        sarr[mt][0] = s0; sarr[mt][1] = s1;
    }
    __syncthreads();
    float* rs = (float*)smem;
    if ((lane & 3) == 0) {
#pragma unroll
        for (int mt = 0; mt < 4; ++mt) {
            rs[wid * 64 + mt * 16 + (lane >> 2)] = sarr[mt][0];
            rs[wid * 64 + mt * 16 + 8 + (lane >> 2)] = sarr[mt][1];
        }
    }
    __syncthreads();
    if (wid < 4) {
        const int rl = wid * 32 + lane;
        const int wm = rl >> 6, idx = rl & 63;
        float sum = rs[(wm + 0) * 64 + idx] + rs[(wm + 2) * 64 + idx]
                  + rs[(wm + 4) * 64 + idx] + rs[(wm + 6) * 64 + idx];
        const int r = rowBase + rl;
        if (r < nrows) outPart[blockIdx.y * nrows + r] = sum;
    }
}

// ================= softmaxes (32 blocks, 512 thr, NPART=6) =================
__global__ __launch_bounds__(512)
void softmax_kernel() {
    __shared__ float red[512];
    __shared__ float w[SS];
    const int b = blockIdx.x, tid = threadIdx.x;

    float s0 = -1e30f;
    if (tid < RR) {
        float s = 0.f;
#pragma unroll
        for (int c = 0; c < NPART; c++) s += g_isc_part[c * NROWS_I + b * RR + tid];
        w[tid] = s; s0 = s;
    }
    float mx = bmax(s0, red);
    float ex = 0.f;
    if (tid < RR) ex = expf(w[tid] - mx);
    float tot = bsum(ex, red);
    if (tid < RR) g_wimg[b * RR + tid] = ex / tot;
    __syncthreads();

    float s = 0.f;
#pragma unroll
    for (int c = 0; c < NPART; c++) s += g_ksc_part[c * MROWS_T + b * SS + tid];
    float mx2 = bmax(s, red);
    float e = expf(s - mx2);
    float tot2 = bsum(e, red);
    g_wtxt[b * SS + tid] = e / tot2;
}

// ================= attend partials: grid (B, 3, SCH), block 128 =================
__global__ __launch_bounds__(128)
void attend_part(const float* __restrict__ img) {
    __shared__ float wt[128];
    __shared__ float wi[RR];
    const int b = blockIdx.x, tid = threadIdx.x;
    const int c = blockIdx.y * 128 + tid;     // half2/float2 column, 0..383
    const int sch = blockIdx.z;
    const int j0 = sch * 128;

    wt[tid] = g_wtxt[b * SS + j0 + tid];
    if (sch == 0 && tid < RR) wi[tid] = g_wimg[b * RR + tid];
    __syncthreads();

    {
        const __half2* tp = (const __half2*)g_tF + (size_t)(b * SS + j0) * (HH / 2) + c;
        float2 a = {0.f, 0.f};
#pragma unroll 8
        for (int j = 0; j < 128; ++j) {
            float2 v = __half22float2(tp[(size_t)j * (HH / 2)]);
            a.x += wt[j] * v.x; a.y += wt[j] * v.y;
        }
        ((float2*)(g_attTp + ((size_t)sch * BB + b) * HH))[c] = a;
    }
    if (sch == 0) {
        const float2* ip = (const float2*)(img + (size_t)b * RR * HH) + c;
        float2 a = {0.f, 0.f};
#pragma unroll
        for (int r = 0; r < RR; ++r) {
            float2 v = ip[(size_t)r * (HH / 2)];
            a.x += wi[r] * v.x; a.y += wi[r] * v.y;
        }
        ((float2*)(g_attI + b * HH))[c] = a;
    }
}

// ================= small GEMM: nI = tanh(attI@gi_w+b), nT = tanh(attT@gt_w+b) ======
__global__ __launch_bounds__(256)
void small_gemm_nit(const float* __restrict__ giw, const float* __restrict__ gib,
                    const float* __restrict__ gtw, const float* __restrict__ gtb) {
    const bool isT = blockIdx.y != 0;
    const float* W = isT ? gtw : giw;
    const float* bias = isT ? gtb : gib;
    float* C = isT ? g_nT : g_nI;

    __shared__ __align__(16) float As[32][36];
    __shared__ __align__(16) float Ws[32][128];
    const int tid = threadIdx.x;
    const int colBase = blockIdx.x * 128;
    const int tx = tid & 31;
    const int ty = tid >> 5;

    float acc[4][4];
#pragma unroll
    for (int i = 0; i < 4; i++)
#pragma unroll
        for (int j = 0; j < 4; j++) acc[i][j] = 0.f;

    for (int kt = 0; kt < HH; kt += 32) {
        {
            int r = tid >> 3;
            int kg = (tid & 7) << 2;
            float4 v;
            if (isT) {
                v = *(const float4*)(g_attTp + (size_t)r * HH + kt + kg);
#pragma unroll
                for (int s = 1; s < SCH; ++s) {
                    float4 p = *(const float4*)(g_attTp + ((size_t)s * BB + r) * HH + kt + kg);
                    v.x += p.x; v.y += p.y; v.z += p.z; v.w += p.w;
                }
            } else {
                v = *(const float4*)(g_attI + (size_t)r * HH + kt + kg);
            }
            As[kg + 0][r] = v.x; As[kg + 1][r] = v.y;
            As[kg + 2][r] = v.z; As[kg + 3][r] = v.w;
        }
#pragma unroll
        for (int i = 0; i < 4; i++) {
            int idx = tid + i * 256;
            int kk = idx >> 5;
            int ng = (idx & 31) << 2;
            *(float4*)&Ws[kk][ng] = *(const float4*)(W + (kt + kk) * HH + colBase + ng);
        }
        __syncthreads();
#pragma unroll
        for (int k = 0; k < 32; k++) {
            float4 av4 = *(const float4*)&As[k][ty * 4];
            float4 w = *(const float4*)&Ws[k][tx * 4];
            float a[4] = {av4.x, av4.y, av4.z, av4.w};
#pragma unroll
            for (int i = 0; i < 4; i++) {
                acc[i][0] = fmaf(a[i], w.x, acc[i][0]);
                acc[i][1] = fmaf(a[i], w.y, acc[i][1]);
                acc[i][2] = fmaf(a[i], w.z, acc[i][2]);
                acc[i][3] = fmaf(a[i], w.w, acc[i][3]);
            }
        }
        __syncthreads();
    }

    int col = colBase + tx * 4;
    float4 bv = *(const float4*)(bias + col);
#pragma unroll
    for (int i = 0; i < 4; i++) {
        int row = ty * 4 + i;
        float4 o;
        o.x = tanhf(acc[i][0] + bv.x);
        o.y = tanhf(acc[i][1] + bv.y);
        o.z = tanhf(acc[i][2] + bv.z);
        o.w = tanhf(acc[i][3] + bv.w);
        *(float4*)(C + row * HH + col) = o;
    }
}

// ================= fr GEMM with fused gate + multimodal + fm score =================
// grid 6 blocks; each computes gate[32] (+block 0 writes fmsc), then
// frout[:, colBase:colBase+128] = tanh(mm @ fr_w + fr_b) with mm built on the fly.
__global__ __launch_bounds__(256)
void fr_gate_gemm(const float* __restrict__ ggw, const float* __restrict__ ggb,
                  const float* __restrict__ fgb, const float* __restrict__ frw,
                  const float* __restrict__ frb) {
    __shared__ float gate_s[32];
    __shared__ __align__(16) float As[32][36];
    __shared__ __align__(16) float Ws[32][128];
    const int tid = threadIdx.x;
    const int b = tid >> 3, sub = tid & 7;   // 8 threads per batch

    // gate
    float gp = 0.f;
    for (int h = sub; h < HH; h += 8)
        gp += g_nI[b * HH + h] * ggw[h] + g_nT[b * HH + h] * ggw[HH + h];
    gp += __shfl_xor_sync(0xffffffffu, gp, 1);
    gp += __shfl_xor_sync(0xffffffffu, gp, 2);
    gp += __shfl_xor_sync(0xffffffffu, gp, 4);
    if (sub == 0) gate_s[b] = 1.f / (1.f + expf(-(gp + ggb[0])));
    __syncthreads();

    // fm score (block 0 writes)
    if (blockIdx.x == 0) {
        const float g = gate_s[b];
        float fmp = 0.f;
        for (int h = sub; h < HH; h += 8) {
            float v = g * g_nI[b * HH + h] + (1.f - g) * g_nT[b * HH + h];
            fmp += v * g_vfm[h];
        }
        fmp += __shfl_xor_sync(0xffffffffu, fmp, 1);
        fmp += __shfl_xor_sync(0xffffffffu, fmp, 2);
        fmp += __shfl_xor_sync(0xffffffffu, fmp, 4);
        if (sub == 0) g_fmsc[b] = fmp + g_fmc + fgb[0];
    }

    // GEMM: frout = tanh(mm @ fr_w + fr_b), A tile built from nI/nT/gate
    const int colBase = blockIdx.x * 128;
    const int tx = tid & 31, ty = tid >> 5;
    float acc[4][4];
#pragma unroll
    for (int i = 0; i < 4; i++)
#pragma unroll
        for (int j = 0; j < 4; j++) acc[i][j] = 0.f;

    for (int kt = 0; kt < HH; kt += 32) {
        {
            int r = tid >> 3;
            int kg = (tid & 7) << 2;
            float4 vi = *(const float4*)(g_nI + r * HH + kt + kg);
            float4 vt = *(const float4*)(g_nT + r * HH + kt + kg);
            float gr = gate_s[r], hr = 1.f - gr;
            As[kg + 0][r] = gr * vi.x + hr * vt.x;
            As[kg + 1][r] = gr * vi.y + hr * vt.y;
            As[kg + 2][r] = gr * vi.z + hr * vt.z;
            As[kg + 3][r] = gr * vi.w + hr * vt.w;
        }
#pragma unroll
        for (int i = 0; i < 4; i++) {
            int idx = tid + i * 256;
            int kk = idx >> 5;
            int ng = (idx & 31) << 2;
            *(float4*)&Ws[kk][ng] = *(const float4*)(frw + (kt + kk) * HH + colBase + ng);
        }
        __syncthreads();
#pragma unroll
        for (int k = 0; k < 32; k++) {
            float4 av4 = *(const float4*)&As[k][ty * 4];
            float4 w = *(const float4*)&Ws[k][tx * 4];
            float a[4] = {av4.x, av4.y, av4.z, av4.w};
#pragma unroll
            for (int i = 0; i < 4; i++) {
                acc[i][0] = fmaf(a[i], w.x, acc[i][0]);
                acc[i][1] = fmaf(a[i], w.y, acc[i][1]);
                acc[i][2] = fmaf(a[i], w.z, acc[i][2]);
                acc[i][3] = fmaf(a[i], w.w, acc[i][3]);
            }
        }
        __syncthreads();
    }

    int col = colBase + tx * 4;
    float4 bv = *(const float4*)(frb + col);
#pragma unroll
    for (int i = 0; i < 4; i++) {
        int row = ty * 4 + i;
        float4 o;
        o.x = tanhf(acc[i][0] + bv.x);
        o.y = tanhf(acc[i][1] + bv.y);
        o.z = tanhf(acc[i][2] + bv.z);
        o.w = tanhf(acc[i][3] + bv.w);
        *(float4*)(g_frout + row * HH + col) = o;
    }
}

// ================= output: warp per row, precomputed fdot =================
__global__ __launch_bounds__(256)
void out_kernel(float* __restrict__ out) {
    const int warp = threadIdx.x >> 5;
    const int lane = threadIdx.x & 31;
    const int row = blockIdx.x * 8 + warp;
    const int b = row >> 9;

    const float fg = 1.f / (1.f + expf(-(g_fdot[row] + g_fmsc[b])));
    const float4* fr = (const float4*)(g_frout + b * HH);
    float4* op = (float4*)(out + (size_t)row * HH);
#pragma unroll
    for (int i = 0; i < 6; i++) {
        float4 f = fr[lane + i * 32];
        float4 o;
        o.x = fg * f.x; o.y = fg * f.y; o.z = fg * f.z; o.w = fg * f.w;
        op[lane + i * 32] = o;
    }
}

// ================= launch =================
extern "C" void kernel_launch(void* const* d_in, const int* in_sizes, int n_in,
                              void* d_out, int out_size) {
    const float* text = (const float*)d_in[0];
    const float* img  = (const float*)d_in[1];
    const float* i1w  = (const float*)d_in[4];
    const float* a1w  = (const float*)d_in[5];
    const float* t2w  = (const float*)d_in[7];
    const float* a2w  = (const float*)d_in[10];
    const float* gtw  = (const float*)d_in[12];
    const float* gtb  = (const float*)d_in[13];
    const float* giw  = (const float*)d_in[14];
    const float* gib  = (const float*)d_in[15];
    const float* ggw  = (const float*)d_in[16];
    const float* ggb  = (const float*)d_in[17];
    const float* ftw  = (const float*)d_in[18];
    const float* fmw  = (const float*)d_in[19];
    const float* fmb  = (const float*)d_in[20];
    const float* fgw  = (const float*)d_in[21];
    const float* fgb  = (const float*)d_in[22];
    const float* frw  = (const float*)d_in[23];
    const float* frb  = (const float*)d_in[24];
    float* out = (float*)d_out;

    float* kscp;  cudaGetSymbolAddress((void**)&kscp,  g_ksc_part);
    float* iscp;  cudaGetSymbolAddress((void**)&iscp,  g_isc_part);
    __half *tF, *iF, *w2, *w1;
    cudaGetSymbolAddress((void**)&tF, g_tF);
    cudaGetSymbolAddress((void**)&iF, g_iF);
    cudaGetSymbolAddress((void**)&w2, g_w2);
    cudaGetSymbolAddress((void**)&w1, g_w1);

    cudaFuncSetAttribute(hmma_tanh_dot, cudaFuncAttributeMaxDynamicSharedMemorySize, HMMA_SMEM);

    // 1. rank-1 collapses (v_ft needed by cvt_prep text part)
    prep_kernel<<<HH, 128>>>(ftw, fmw, fmb, fgw);

    // 2. fp16 conversions + fgate dot + weight transposes (one launch)
    cvt_prep<<<2244 + 1152, 256>>>(text, img, t2w, i1w);

    // 3. merged text + img GEMM partials
    {
        dim3 g(TXB + MROWS_I / 128, HH / 128);
        hmma_tanh_dot<<<g, 256, HMMA_SMEM>>>(tF, iF, w2, w1, a2w + HH, a1w + HH, kscp, iscp);
    }

    // 4. softmaxes
    softmax_kernel<<<BB, 512>>>();

    // 5. attended-vector partials (wide)
    {
        dim3 g(BB, 3, SCH);
        attend_part<<<g, 128>>>(img);
    }

    // 6. nI/nT small GEMMs (sums attT partials in the A loader)
    {
        dim3 g(NCB, 2);
        small_gemm_nit<<<g, 256>>>(giw, gib, gtw, gtb);
    }

    // 7. gate + multimodal + fm score + fr GEMM (fused)
    fr_gate_gemm<<<NCB, 256>>>(ggw, ggb, fgb, frw, frb);

    // 8. output
    out_kernel<<<(BB * SS) / 8, 256>>>(out);
}

// round 16
// speedup vs baseline: 1.2006x; 1.1883x over previous
#include <cuda_runtime.h>
#include <cuda_fp16.h>
#include <stdint.h>

#define BB 32
#define SS 512
#define RR 49
#define HH 768
#define NCB 6              // 128-col blocks for small_gemm
#define NPART 6            // 128-col partial groups for the tensor GEMM (post-reduce)
#define MROWS_T (BB*SS)    // 16384
#define NROWS_I (BB*RR)    // 1568
#define MROWS_I 1664       // padded to 13*128
#define TXB (MROWS_T/128)  // 128 text row-blocks
#define SCH 4              // S-chunks for attend

// ================= PTX helpers =================
__device__ __forceinline__ uint32_t smem_u32(const void* p) {
    uint32_t a;
    asm("{ .reg .u64 t; cvta.to.shared.u64 t, %1; cvt.u32.u64 %0, t; }" : "=r"(a) : "l"(p));
    return a;
}
#define SMEM_SWIZZLE_128B(x) ((x) ^ (((x) >> 3) & 0x70))

__device__ __forceinline__ void cpa16(uint32_t s, const void* g) {
    asm volatile("cp.async.cg.shared.global [%0], [%1], 16;" :: "r"(s), "l"(g));
}
__device__ __forceinline__ void ldmx4(uint32_t* r, uint32_t addr) {
    asm volatile("ldmatrix.sync.aligned.m8n8.x4.shared.b16 {%0,%1,%2,%3}, [%4];"
                 : "=r"(r[0]), "=r"(r[1]), "=r"(r[2]), "=r"(r[3]) : "r"(addr));
}
__device__ __forceinline__ void mma16816(float* c, const uint32_t* a, uint32_t b0, uint32_t b1) {
    asm volatile(
        "mma.sync.aligned.m16n8k16.row.col.f32.f16.f16.f32 "
        "{%0,%1,%2,%3}, {%4,%5,%6,%7}, {%8,%9}, {%0,%1,%2,%3};"
        : "+f"(c[0]), "+f"(c[1]), "+f"(c[2]), "+f"(c[3])
        : "r"(a[0]), "r"(a[1]), "r"(a[2]), "r"(a[3]), "r"(b0), "r"(b1));
}
__device__ __forceinline__ float fast_tanh(float x) {
    const float e = __expf(2.f * x);
    return 1.f - __fdividef(2.f, e + 1.f);
}

// ================= scratch (device globals) =================
__device__ float g_ksc_part[NPART * MROWS_T];
__device__ float g_isc_part[NPART * NROWS_I];
__device__ __align__(16) float g_vft[HH];
__device__ __align__(16) float g_vfm[HH];
__device__ float g_fmc;
__device__ float g_fmsc[BB];
__device__ float g_fdot[MROWS_T];
__device__ __align__(16) float g_frout[BB * HH];
__device__ float g_wimg[BB * RR];
__device__ float g_wtxt[BB * SS];
__device__ __align__(16) float g_attI[BB * HH];
__device__ __align__(16) float g_attTp[SCH * BB * HH];   // att_text partials per S-chunk
__device__ __align__(16) float g_nI[BB * HH];
__device__ __align__(16) float g_nT[BB * HH];
__device__ __align__(16) float g_mm[BB * HH];
// fp16 inputs + weights (transposed [n][k])
__device__ __align__(16) __half g_tF[MROWS_T * HH];
__device__ __align__(16) __half g_iF[MROWS_I * HH];   // pad rows stay zero
__device__ __align__(16) __half g_w2[HH * HH];
__device__ __align__(16) __half g_w1[HH * HH];

// ================= block reduce helpers =================
__device__ __forceinline__ float bsum(float v, float* sm) {
    int tid = threadIdx.x;
    sm[tid] = v; __syncthreads();
    for (int s = blockDim.x >> 1; s > 0; s >>= 1) {
        if (tid < s) sm[tid] += sm[tid + s];
        __syncthreads();
    }
    float r = sm[0]; __syncthreads();
    return r;
}
__device__ __forceinline__ float bmax(float v, float* sm) {
    int tid = threadIdx.x;
    sm[tid] = v; __syncthreads();
    for (int s = blockDim.x >> 1; s > 0; s >>= 1) {
        if (tid < s) sm[tid] = fmaxf(sm[tid], sm[tid + s]);
        __syncthreads();
    }
    float r = sm[0]; __syncthreads();
    return r;
}

// ================= prep: rank-1 collapses =================
__global__ void prep_kernel(const float* __restrict__ ftw, const float* __restrict__ fmw,
                            const float* __restrict__ fmb, const float* __restrict__ fgw) {
    __shared__ float red[128];
    const int k = blockIdx.x, tid = threadIdx.x;
    float s1 = 0.f, s2 = 0.f, s3 = 0.f;
    for (int h = tid; h < HH; h += 128) {
        float g1 = fgw[h], g2 = fgw[HH + h];
        s1 += ftw[k * HH + h] * g1;
        s2 += fmw[k * HH + h] * g2;
        if (k == 0) s3 += fmb[h] * g2;
    }
    float t1 = bsum(s1, red);
    float t2 = bsum(s2, red);
    if (tid == 0) { g_vft[k] = t1; g_vfm[k] = t2; }
    if (k == 0) {
        float t3 = bsum(s3, red);
        if (tid == 0) g_fmc = t3;
    }
}

// ================= cvt_prep: fp32->fp16 conversions + fgate dot + weight transpose ==
// blocks [0,2048): text warp-per-row (+dot with v_ft)
// blocks [2048,2244): img warp-per-row
// blocks [2244,3396): weight transpose tcvt (1152 = 576 per weight, 24x24 tiles)
__global__ __launch_bounds__(256)
void cvt_prep(const float* __restrict__ text, const float* __restrict__ img,
              const float* __restrict__ t2w, const float* __restrict__ i1w) {
    const int bx = blockIdx.x, tid = threadIdx.x;
    if (bx < 2048) {
        const int warp = tid >> 5, lane = tid & 31;
        const int row = bx * 8 + warp;
        const float4* tv = (const float4*)(text + (size_t)row * HH);
        uint2* tout = (uint2*)(g_tF + (size_t)row * HH);
        const float4* vv = (const float4*)g_vft;
        float p = 0.f;
#pragma unroll
        for (int i = 0; i < 6; i++) {
            float4 v = tv[lane + i * 32];
            float4 f = vv[lane + i * 32];
            p += v.x * f.x + v.y * f.y + v.z * f.z + v.w * f.w;
            union { __half h[4]; uint2 u; } H;
            H.h[0] = __float2half(v.x); H.h[1] = __float2half(v.y);
            H.h[2] = __float2half(v.z); H.h[3] = __float2half(v.w);
            tout[lane + i * 32] = H.u;
        }
#pragma unroll
        for (int off = 16; off > 0; off >>= 1) p += __shfl_xor_sync(0xffffffffu, p, off);
        if (lane == 0) g_fdot[row] = p;
    } else if (bx < 2244) {
        const int warp = tid >> 5, lane = tid & 31;
        const int row = (bx - 2048) * 8 + warp;     // 0..1567
        const float4* iv = (const float4*)(img + (size_t)row * HH);
        uint2* iout = (uint2*)(g_iF + (size_t)row * HH);
#pragma unroll
        for (int i = 0; i < 6; i++) {
            float4 v = iv[lane + i * 32];
            union { __half h[4]; uint2 u; } H;
            H.h[0] = __float2half(v.x); H.h[1] = __float2half(v.y);
            H.h[2] = __float2half(v.z); H.h[3] = __float2half(v.w);
            iout[lane + i * 32] = H.u;
        }
    } else {
        __shared__ float t[32][33];
        const int tt0 = bx - 2244;
        const int z = tt0 >= 576;
        const int tt = z ? tt0 - 576 : tt0;
        const float* W = z ? i1w : t2w;
        __half* Hi = z ? g_w1 : g_w2;
        const int kb = (tt / 24) * 32, nb = (tt % 24) * 32;
        const int tx = tid & 31, ty = tid >> 5;
#pragma unroll
        for (int i = 0; i < 4; ++i)
            t[ty + 8 * i][tx] = W[(size_t)(kb + ty + 8 * i) * HH + nb + tx];
        __syncthreads();
#pragma unroll
        for (int i = 0; i < 4; ++i)
            Hi[(size_t)(nb + ty + 8 * i) * HH + kb + tx] = __float2half(t[tx][ty + 8 * i]);
    }
}

// ================= single-pass fp16 HMMA GEMM + tanh + dot epilogue =================
// Merged launch: blockIdx.x < TXB -> text GEMM; else img GEMM.
// Epilogue reduces across the 4 warpn groups via smem -> ONE partial per 128-col block.
#define HMMA_SMEM (96 * 1024)

__device__ __forceinline__ void issue_chunk(
    const __half* __restrict__ Ap, const __half* __restrict__ Bp,
    int kt, uint32_t stageBase, int tid, int rowBase, int colBase) {
#pragma unroll
    for (int i = 0; i < 4; i++) {
        int u = tid + i * 256;
        cpa16(stageBase + SMEM_SWIZZLE_128B((uint32_t)u * 16u),
              Ap + (size_t)(rowBase + (u >> 3)) * HH + kt + (u & 7) * 8);
    }
#pragma unroll
    for (int i = 0; i < 4; i++) {
        int u = tid + i * 256;
        cpa16(stageBase + 16384u + SMEM_SWIZZLE_128B((uint32_t)u * 16u),
              Bp + (size_t)(colBase + (u >> 3)) * HH + kt + (u & 7) * 8);
    }
    asm volatile("cp.async.commit_group;");
}

__global__ __launch_bounds__(256, 2)
void hmma_tanh_dot(const __half* __restrict__ AT, const __half* __restrict__ AI,
                   const __half* __restrict__ WT, const __half* __restrict__ WI,
                   const float* __restrict__ avT, const float* __restrict__ avI,
                   float* __restrict__ outT, float* __restrict__ outI) {
    extern __shared__ __align__(1024) char smem[];
    const uint32_t sb = smem_u32(smem);
    const int tid = threadIdx.x;
    const int wid = tid >> 5, lane = tid & 31;
    const int warpm = wid & 1, warpn = wid >> 1;
    const int bx = blockIdx.x;
    const bool isT = bx < TXB;
    const __half* A = isT ? AT : AI;
    const __half* W = isT ? WT : WI;
    const float* av = isT ? avT : avI;
    float* outPart = isT ? outT : outI;
    const int nrows = isT ? MROWS_T : NROWS_I;
    const int rowBase = (isT ? bx : bx - TXB) * 128;
    const int colBase = blockIdx.y * 128;

    float acc[4][4][4];
#pragma unroll
    for (int i = 0; i < 4; i++)
#pragma unroll
        for (int j = 0; j < 4; j++)
#pragma unroll
            for (int q = 0; q < 4; q++) acc[i][j][q] = 0.f;

    issue_chunk(A, W, 0, sb, tid, rowBase, colBase);
    issue_chunk(A, W, 64, sb + 32768u, tid, rowBase, colBase);

    for (int it = 0; it < 12; ++it) {
        if (it < 11) asm volatile("cp.async.wait_group 1;");
        else         asm volatile("cp.async.wait_group 0;");
        __syncthreads();
        if (it < 10)
            issue_chunk(A, W, (it + 2) * 64, sb + (uint32_t)((it + 2) % 3) * 32768u,
                        tid, rowBase, colBase);

        const uint32_t abase = sb + (uint32_t)(it % 3) * 32768u;
        const uint32_t bbase = abase + 16384u;
#pragma unroll
        for (int ks = 0; ks < 4; ++ks) {
            uint32_t bf[2][4];
#pragma unroll
            for (int g = 0; g < 2; ++g) {
                const int n = warpn * 32 + g * 16 + (lane & 7) + ((lane >> 4) << 3);
                const int kb = ks * 32 + ((lane >> 3) & 1) * 16;
                ldmx4(bf[g], bbase + SMEM_SWIZZLE_128B((uint32_t)(n * 128 + kb)));
            }
#pragma unroll
            for (int mt = 0; mt < 4; ++mt) {
                uint32_t a[4];
                const int r = warpm * 64 + mt * 16 + (lane & 15);
                const int kb = ks * 32 + ((lane >> 4) << 4);
                ldmx4(a, abase + SMEM_SWIZZLE_128B((uint32_t)(r * 128 + kb)));
#pragma unroll
                for (int nt = 0; nt < 4; ++nt)
                    mma16816(acc[mt][nt], a, bf[nt >> 1][(nt & 1) * 2],
                             bf[nt >> 1][(nt & 1) * 2 + 1]);
            }
        }
    }

    // ---- epilogue: tanh * av per warp, then cross-warpn reduction via smem ----
    const float* avp = av + colBase + warpn * 32;
    float avv[4][2];
#pragma unroll
    for (int nt = 0; nt < 4; ++nt) {
        avv[nt][0] = avp[nt * 8 + (lane & 3) * 2];
        avv[nt][1] = avp[nt * 8 + (lane & 3) * 2 + 1];
    }
    float sarr[4][2];
#pragma unroll
    for (int mt = 0; mt < 4; ++mt) {
        float s0 = 0.f, s1 = 0.f;
#pragma unroll
        for (int nt = 0; nt < 4; ++nt) {
            s0 += fast_tanh(acc[mt][nt][0]) * avv[nt][0] + fast_tanh(acc[mt][nt][1]) * avv[nt][1];
            s1 += fast_tanh(acc[mt][nt][2]) * avv[nt][0] + fast_tanh(acc[mt][nt][3]) * avv[nt][1];
        }
        s0 += __shfl_xor_sync(0xffffffffu, s0, 1);
        s0 += __shfl_xor_sync(0xffffffffu, s0, 2);
        s1 += __shfl_xor_sync(0xffffffffu, s1, 1);
        s1 += __shfl_xor_sync(0xffffffffu, s1, 2);
        sarr[mt][0] = s0; sarr[mt][1] = s1;
    }
    __syncthreads();              // all warps done with mainloop smem reads
    float* rs = (float*)smem;     // [8 warps][64 local rows]
    if ((lane & 3) == 0) {
#pragma unroll
        for (int mt = 0; mt < 4; ++mt) {
            rs[wid * 64 + mt * 16 + (lane >> 2)] = sarr[mt][0];
            rs[wid * 64 + mt * 16 + 8 + (lane >> 2)] = sarr[mt][1];
        }
    }
    __syncthreads();
    if (wid < 4) {
        const int rl = wid * 32 + lane;      // local row 0..127
        const int wm = rl >> 6, idx = rl & 63;
        float sum = rs[(wm + 0) * 64 + idx] + rs[(wm + 2) * 64 + idx]
                  + rs[(wm + 4) * 64 + idx] + rs[(wm + 6) * 64 + idx];
        const int r = rowBase + rl;
        if (r < nrows) outPart[blockIdx.y * nrows + r] = sum;
    }
}

// ================= softmaxes (32 blocks, 512 thr, NPART=6) =================
__global__ __launch_bounds__(512)
void softmax_kernel() {
    __shared__ float red[512];
    __shared__ float w[SS];
    const int b = blockIdx.x, tid = threadIdx.x;

    float s0 = -1e30f;
    if (tid < RR) {
        float s = 0.f;
#pragma unroll
        for (int c = 0; c < NPART; c++) s += g_isc_part[c * NROWS_I + b * RR + tid];
        w[tid] = s; s0 = s;
    }
    float mx = bmax(s0, red);
    float ex = 0.f;
    if (tid < RR) ex = expf(w[tid] - mx);
    float tot = bsum(ex, red);
    if (tid < RR) g_wimg[b * RR + tid] = ex / tot;
    __syncthreads();

    // textual: one thread per S position
    float s = 0.f;
#pragma unroll
    for (int c = 0; c < NPART; c++) s += g_ksc_part[c * MROWS_T + b * SS + tid];
    float mx2 = bmax(s, red);
    float e = expf(s - mx2);
    float tot2 = bsum(e, red);
    g_wtxt[b * SS + tid] = e / tot2;
}

// ================= attend partials: grid (B, 3, SCH), block 128 =================
__global__ __launch_bounds__(128)
void attend_part(const float* __restrict__ img) {
    __shared__ float wt[128];
    __shared__ float wi[RR];
    const int b = blockIdx.x, tid = threadIdx.x;
    const int c = blockIdx.y * 128 + tid;     // half2/float2 column, 0..383
    const int sch = blockIdx.z;
    const int j0 = sch * 128;

    wt[tid] = g_wtxt[b * SS + j0 + tid];
    if (sch == 0 && tid < RR) wi[tid] = g_wimg[b * RR + tid];
    __syncthreads();

    {
        const __half2* tp = (const __half2*)g_tF + (size_t)(b * SS + j0) * (HH / 2) + c;
        float2 a = {0.f, 0.f};
#pragma unroll 8
        for (int j = 0; j < 128; ++j) {
            float2 v = __half22float2(tp[(size_t)j * (HH / 2)]);
            a.x += wt[j] * v.x; a.y += wt[j] * v.y;
        }
        ((float2*)(g_attTp + ((size_t)sch * BB + b) * HH))[c] = a;
    }
    if (sch == 0) {
        const float2* ip = (const float2*)(img + (size_t)b * RR * HH) + c;
        float2 a = {0.f, 0.f};
#pragma unroll
        for (int r = 0; r < RR; ++r) {
            float2 v = ip[(size_t)r * (HH / 2)];
            a.x += wi[r] * v.x; a.y += wi[r] * v.y;
        }
        ((float2*)(g_attI + b * HH))[c] = a;
    }
}

// ================= small GEMM: nI = tanh(attI@gi_w+b), nT = tanh(attT@gt_w+b) ======
__global__ __launch_bounds__(256)
void small_gemm_nit(const float* __restrict__ giw, const float* __restrict__ gib,
                    const float* __restrict__ gtw, const float* __restrict__ gtb) {
    const bool isT = blockIdx.y != 0;
    const float* W = isT ? gtw : giw;
    const float* bias = isT ? gtb : gib;
    float* C = isT ? g_nT : g_nI;

    __shared__ __align__(16) float As[32][36];
    __shared__ __align__(16) float Ws[32][128];
    const int tid = threadIdx.x;
    const int colBase = blockIdx.x * 128;
    const int tx = tid & 31;
    const int ty = tid >> 5;

    float acc[4][4];
#pragma unroll
    for (int i = 0; i < 4; i++)
#pragma unroll
        for (int j = 0; j < 4; j++) acc[i][j] = 0.f;

    for (int kt = 0; kt < HH; kt += 32) {
        {
            int r = tid >> 3;
            int kg = (tid & 7) << 2;
            float4 v;
            if (isT) {
                v = *(const float4*)(g_attTp + (size_t)r * HH + kt + kg);
#pragma unroll
                for (int s = 1; s < SCH; ++s) {
                    float4 p = *(const float4*)(g_attTp + ((size_t)s * BB + r) * HH + kt + kg);
                    v.x += p.x; v.y += p.y; v.z += p.z; v.w += p.w;
                }
            } else {
                v = *(const float4*)(g_attI + (size_t)r * HH + kt + kg);
            }
            As[kg + 0][r] = v.x; As[kg + 1][r] = v.y;
            As[kg + 2][r] = v.z; As[kg + 3][r] = v.w;
        }
#pragma unroll
        for (int i = 0; i < 4; i++) {
            int idx = tid + i * 256;
            int kk = idx >> 5;
            int ng = (idx & 31) << 2;
            *(float4*)&Ws[kk][ng] = *(const float4*)(W + (kt + kk) * HH + colBase + ng);
        }
        __syncthreads();
#pragma unroll
        for (int k = 0; k < 32; k++) {
            float4 av4 = *(const float4*)&As[k][ty * 4];
            float4 w = *(const float4*)&Ws[k][tx * 4];
            float a[4] = {av4.x, av4.y, av4.z, av4.w};
#pragma unroll
            for (int i = 0; i < 4; i++) {
                acc[i][0] = fmaf(a[i], w.x, acc[i][0]);
                acc[i][1] = fmaf(a[i], w.y, acc[i][1]);
                acc[i][2] = fmaf(a[i], w.z, acc[i][2]);
                acc[i][3] = fmaf(a[i], w.w, acc[i][3]);
            }
        }
        __syncthreads();
    }

    int col = colBase + tx * 4;
    float4 bv = *(const float4*)(bias + col);
#pragma unroll
    for (int i = 0; i < 4; i++) {
        int row = ty * 4 + i;
        float4 o;
        o.x = tanhf(acc[i][0] + bv.x);
        o.y = tanhf(acc[i][1] + bv.y);
        o.z = tanhf(acc[i][2] + bv.z);
        o.w = tanhf(acc[i][3] + bv.w);
        *(float4*)(C + row * HH + col) = o;
    }
}

// ================= small GEMM (generic): C[32,768] = tanh(A @ W + bias) ============
__global__ __launch_bounds__(256)
void small_gemm_tanh(const float* __restrict__ A, const float* __restrict__ W,
                     const float* __restrict__ bias, float* __restrict__ C) {
    __shared__ __align__(16) float As[32][36];
    __shared__ __align__(16) float Ws[32][128];
    const int tid = threadIdx.x;
    const int colBase = blockIdx.x * 128;
    const int tx = tid & 31;
    const int ty = tid >> 5;

    float acc[4][4];
#pragma unroll
    for (int i = 0; i < 4; i++)
#pragma unroll
        for (int j = 0; j < 4; j++) acc[i][j] = 0.f;

    for (int kt = 0; kt < HH; kt += 32) {
        {
            int r = tid >> 3;
            int kg = (tid & 7) << 2;
            float4 v = *(const float4*)(A + r * HH + kt + kg);
            As[kg + 0][r] = v.x; As[kg + 1][r] = v.y;
            As[kg + 2][r] = v.z; As[kg + 3][r] = v.w;
        }
#pragma unroll
        for (int i = 0; i < 4; i++) {
            int idx = tid + i * 256;
            int kk = idx >> 5;
            int ng = (idx & 31) << 2;
            *(float4*)&Ws[kk][ng] = *(const float4*)(W + (kt + kk) * HH + colBase + ng);
        }
        __syncthreads();
#pragma unroll
        for (int k = 0; k < 32; k++) {
            float4 av4 = *(const float4*)&As[k][ty * 4];
            float4 w = *(const float4*)&Ws[k][tx * 4];
            float a[4] = {av4.x, av4.y, av4.z, av4.w};
#pragma unroll
            for (int i = 0; i < 4; i++) {
                acc[i][0] = fmaf(a[i], w.x, acc[i][0]);
                acc[i][1] = fmaf(a[i], w.y, acc[i][1]);
                acc[i][2] = fmaf(a[i], w.z, acc[i][2]);
                acc[i][3] = fmaf(a[i], w.w, acc[i][3]);
            }
        }
        __syncthreads();
    }

    int col = colBase + tx * 4;
    float4 bv = *(const float4*)(bias + col);
#pragma unroll
    for (int i = 0; i < 4; i++) {
        int row = ty * 4 + i;
        float4 o;
        o.x = tanhf(acc[i][0] + bv.x);
        o.y = tanhf(acc[i][1] + bv.y);
        o.z = tanhf(acc[i][2] + bv.z);
        o.w = tanhf(acc[i][3] + bv.w);
        *(float4*)(C + row * HH + col) = o;
    }
}

// ================= gate + multimodal + fm score =================
__global__ void gate_mm_kernel(const float* __restrict__ ggw, const float* __restrict__ ggb,
                               const float* __restrict__ fgb) {
    __shared__ float red[256];
    const int b = blockIdx.x, tid = threadIdx.x;

    float gp = 0.f;
    for (int h = tid; h < HH; h += 256)
        gp += g_nI[b * HH + h] * ggw[h] + g_nT[b * HH + h] * ggw[HH + h];
    float gs = bsum(gp, red);
    float gate = 1.f / (1.f + expf(-(gs + ggb[0])));

    float fmp = 0.f;
    for (int h = tid; h < HH; h += 256) {
        float v = gate * g_nI[b * HH + h] + (1.f - gate) * g_nT[b * HH + h];
        g_mm[b * HH + h] = v;
        fmp += v * g_vfm[h];
    }
    float fsum = bsum(fmp, red);
    if (tid == 0) g_fmsc[b] = fsum + g_fmc + fgb[0];
}

// ================= output: warp per row, precomputed fdot, streaming stores ========
__global__ __launch_bounds__(256)
void out_kernel(float* __restrict__ out) {
    const int warp = threadIdx.x >> 5;
    const int lane = threadIdx.x & 31;
    const int row = blockIdx.x * 8 + warp;
    const int b = row >> 9;

    const float fg = 1.f / (1.f + expf(-(g_fdot[row] + g_fmsc[b])));
    const float4* fr = (const float4*)(g_frout + b * HH);
    float4* op = (float4*)(out + (size_t)row * HH);
#pragma unroll
    for (int i = 0; i < 6; i++) {
        float4 f = fr[lane + i * 32];
        float4 o;
        o.x = fg * f.x; o.y = fg * f.y; o.z = fg * f.z; o.w = fg * f.w;
        __stcs(op + lane + i * 32, o);     // write-once: evict-first
    }
}

// ================= launch =================
extern "C" void kernel_launch(void* const* d_in, const int* in_sizes, int n_in,
                              void* d_out, int out_size) {
    const float* text = (const float*)d_in[0];
    const float* img  = (const float*)d_in[1];
    const float* i1w  = (const float*)d_in[4];
    const float* a1w  = (const float*)d_in[5];
    const float* t2w  = (const float*)d_in[7];
    const float* a2w  = (const float*)d_in[10];
    const float* gtw  = (const float*)d_in[12];
    const float* gtb  = (const float*)d_in[13];
    const float* giw  = (const float*)d_in[14];
    const float* gib  = (const float*)d_in[15];
    const float* ggw  = (const float*)d_in[16];
    const float* ggb  = (const float*)d_in[17];
    const float* ftw  = (const float*)d_in[18];
    const float* fmw  = (const float*)d_in[19];
    const float* fmb  = (const float*)d_in[20];
    const float* fgw  = (const float*)d_in[21];
    const float* fgb  = (const float*)d_in[22];
    const float* frw  = (const float*)d_in[23];
    const float* frb  = (const float*)d_in[24];
    float* out = (float*)d_out;

    float* mm;    cudaGetSymbolAddress((void**)&mm,    g_mm);
    float* frout; cudaGetSymbolAddress((void**)&frout, g_frout);
    float* kscp;  cudaGetSymbolAddress((void**)&kscp,  g_ksc_part);
    float* iscp;  cudaGetSymbolAddress((void**)&iscp,  g_isc_part);
    __half *tF, *iF, *w2, *w1;
    cudaGetSymbolAddress((void**)&tF, g_tF);
    cudaGetSymbolAddress((void**)&iF, g_iF);
    cudaGetSymbolAddress((void**)&w2, g_w2);
    cudaGetSymbolAddress((void**)&w1, g_w1);

    cudaFuncSetAttribute(hmma_tanh_dot, cudaFuncAttributeMaxDynamicSharedMemorySize, HMMA_SMEM);

    // 1. rank-1 collapses (v_ft needed by cvt_prep text part)
    prep_kernel<<<HH, 128>>>(ftw, fmw, fmb, fgw);

    // 2. fp16 conversions + fgate dot + weight transposes (one launch)
    cvt_prep<<<2244 + 1152, 256>>>(text, img, t2w, i1w);

    // 3. merged text + img GEMM partials
    {
        dim3 g(TXB + MROWS_I / 128, HH / 128);
        hmma_tanh_dot<<<g, 256, HMMA_SMEM>>>(tF, iF, w2, w1, a2w + HH, a1w + HH, kscp, iscp);
    }

    // 4. softmaxes
    softmax_kernel<<<BB, 512>>>();

    // 5. attended-vector partials (wide)
    {
        dim3 g(BB, 3, SCH);
        attend_part<<<g, 128>>>(img);
    }

    // 6. nI/nT small GEMMs (sums attT partials in the A loader)
    {
        dim3 g(NCB, 2);
        small_gemm_nit<<<g, 256>>>(giw, gib, gtw, gtb);
    }

    // 7. gate + multimodal + fm score
    gate_mm_kernel<<<BB, 256>>>(ggw, ggb, fgb);

    // 8. fr_out = tanh(mm @ fr_w + fr_b)
    small_gemm_tanh<<<NCB, 256>>>(mm, frw, frb, frout);

    // 9. output
    out_kernel<<<(BB * SS) / 8, 256>>>(out);
}

// round 17
// speedup vs baseline: 1.2282x; 1.0230x over previous
#include <cuda_runtime.h>
#include <cuda_fp16.h>
#include <stdint.h>

#define BB 32
#define SS 512
#define RR 49
#define HH 768
#define NCB 6              // 128-col blocks for small_gemm
#define NPART 6            // 128-col partial groups for the tensor GEMM (post-reduce)
#define MROWS_T (BB*SS)    // 16384
#define NROWS_I (BB*RR)    // 1568
#define MROWS_I 1664       // padded to 13*128
#define TXB (MROWS_T/128)  // 128 text row-blocks
#define SCH 4              // S-chunks for attend

// ================= PTX helpers =================
__device__ __forceinline__ uint32_t smem_u32(const void* p) {
    uint32_t a;
    asm("{ .reg .u64 t; cvta.to.shared.u64 t, %1; cvt.u32.u64 %0, t; }" : "=r"(a) : "l"(p));
    return a;
}
#define SMEM_SWIZZLE_128B(x) ((x) ^ (((x) >> 3) & 0x70))

__device__ __forceinline__ void cpa16(uint32_t s, const void* g) {
    asm volatile("cp.async.cg.shared.global [%0], [%1], 16;" :: "r"(s), "l"(g));
}
__device__ __forceinline__ void ldmx4(uint32_t* r, uint32_t addr) {
    asm volatile("ldmatrix.sync.aligned.m8n8.x4.shared.b16 {%0,%1,%2,%3}, [%4];"
                 : "=r"(r[0]), "=r"(r[1]), "=r"(r[2]), "=r"(r[3]) : "r"(addr));
}
__device__ __forceinline__ void mma16816(float* c, const uint32_t* a, uint32_t b0, uint32_t b1) {
    asm volatile(
        "mma.sync.aligned.m16n8k16.row.col.f32.f16.f16.f32 "
        "{%0,%1,%2,%3}, {%4,%5,%6,%7}, {%8,%9}, {%0,%1,%2,%3};"
        : "+f"(c[0]), "+f"(c[1]), "+f"(c[2]), "+f"(c[3])
        : "r"(a[0]), "r"(a[1]), "r"(a[2]), "r"(a[3]), "r"(b0), "r"(b1));
}
__device__ __forceinline__ float fast_tanh(float x) {
    const float e = __expf(2.f * x);
    return 1.f - __fdividef(2.f, e + 1.f);
}

// ================= scratch (device globals) =================
__device__ float g_ksc_part[NPART * MROWS_T];
__device__ float g_isc_part[NPART * NROWS_I];
__device__ __align__(16) float g_vft[HH];
__device__ __align__(16) float g_vfm[HH];
__device__ float g_fmc;
__device__ float g_fmsc[BB];
__device__ float g_fdot[MROWS_T];
__device__ __align__(16) float g_frout[BB * HH];
__device__ __align__(16) float g_attI[BB * HH];
__device__ __align__(16) float g_attTp[SCH * BB * HH];   // att_text partials per S-chunk
__device__ __align__(16) float g_nI[BB * HH];
__device__ __align__(16) float g_nT[BB * HH];
__device__ __align__(16) float g_mm[BB * HH];
// fp16 inputs + weights (transposed [n][k])
__device__ __align__(16) __half g_tF[MROWS_T * HH];
__device__ __align__(16) __half g_iF[MROWS_I * HH];   // pad rows stay zero
__device__ __align__(16) __half g_w2[HH * HH];
__device__ __align__(16) __half g_w1[HH * HH];

// ================= block reduce helpers =================
__device__ __forceinline__ float bsum(float v, float* sm) {
    int tid = threadIdx.x;
    sm[tid] = v; __syncthreads();
    for (int s = blockDim.x >> 1; s > 0; s >>= 1) {
        if (tid < s) sm[tid] += sm[tid + s];
        __syncthreads();
    }
    float r = sm[0]; __syncthreads();
    return r;
}
__device__ __forceinline__ float bmax(float v, float* sm) {
    int tid = threadIdx.x;
    sm[tid] = v; __syncthreads();
    for (int s = blockDim.x >> 1; s > 0; s >>= 1) {
        if (tid < s) sm[tid] = fmaxf(sm[tid], sm[tid + s]);
        __syncthreads();
    }
    float r = sm[0]; __syncthreads();
    return r;
}

// ================= prep: rank-1 collapses =================
__global__ void prep_kernel(const float* __restrict__ ftw, const float* __restrict__ fmw,
                            const float* __restrict__ fmb, const float* __restrict__ fgw) {
    __shared__ float red[128];
    const int k = blockIdx.x, tid = threadIdx.x;
    float s1 = 0.f, s2 = 0.f, s3 = 0.f;
    for (int h = tid; h < HH; h += 128) {
        float g1 = fgw[h], g2 = fgw[HH + h];
        s1 += ftw[k * HH + h] * g1;
        s2 += fmw[k * HH + h] * g2;
        if (k == 0) s3 += fmb[h] * g2;
    }
    float t1 = bsum(s1, red);
    float t2 = bsum(s2, red);
    if (tid == 0) { g_vft[k] = t1; g_vfm[k] = t2; }
    if (k == 0) {
        float t3 = bsum(s3, red);
        if (tid == 0) g_fmc = t3;
    }
}

// ================= cvt_prep: fp32->fp16 conversions + fgate dot + weight transpose ==
// blocks [0,2048): text warp-per-row (+dot with v_ft); streaming reads
// blocks [2048,2244): img warp-per-row
// blocks [2244,3396): weight transpose (1152 = 576 per weight, 24x24 tiles)
__global__ __launch_bounds__(256)
void cvt_prep(const float* __restrict__ text, const float* __restrict__ img,
              const float* __restrict__ t2w, const float* __restrict__ i1w) {
    const int bx = blockIdx.x, tid = threadIdx.x;
    if (bx < 2048) {
        const int warp = tid >> 5, lane = tid & 31;
        const int row = bx * 8 + warp;
        const float4* tv = (const float4*)(text + (size_t)row * HH);
        uint2* tout = (uint2*)(g_tF + (size_t)row * HH);
        const float4* vv = (const float4*)g_vft;
        float p = 0.f;
#pragma unroll
        for (int i = 0; i < 6; i++) {
            float4 v = __ldcs(tv + lane + i * 32);    // read-once: evict-first
            float4 f = vv[lane + i * 32];
            p += v.x * f.x + v.y * f.y + v.z * f.z + v.w * f.w;
            union { __half h[4]; uint2 u; } H;
            H.h[0] = __float2half(v.x); H.h[1] = __float2half(v.y);
            H.h[2] = __float2half(v.z); H.h[3] = __float2half(v.w);
            tout[lane + i * 32] = H.u;
        }
#pragma unroll
        for (int off = 16; off > 0; off >>= 1) p += __shfl_xor_sync(0xffffffffu, p, off);
        if (lane == 0) g_fdot[row] = p;
    } else if (bx < 2244) {
        const int warp = tid >> 5, lane = tid & 31;
        const int row = (bx - 2048) * 8 + warp;     // 0..1567
        const float4* iv = (const float4*)(img + (size_t)row * HH);
        uint2* iout = (uint2*)(g_iF + (size_t)row * HH);
#pragma unroll
        for (int i = 0; i < 6; i++) {
            float4 v = iv[lane + i * 32];
            union { __half h[4]; uint2 u; } H;
            H.h[0] = __float2half(v.x); H.h[1] = __float2half(v.y);
            H.h[2] = __float2half(v.z); H.h[3] = __float2half(v.w);
            iout[lane + i * 32] = H.u;
        }
    } else {
        __shared__ float t[32][33];
        const int tt0 = bx - 2244;
        const int z = tt0 >= 576;
        const int tt = z ? tt0 - 576 : tt0;
        const float* W = z ? i1w : t2w;
        __half* Hi = z ? g_w1 : g_w2;
        const int kb = (tt / 24) * 32, nb = (tt % 24) * 32;
        const int tx = tid & 31, ty = tid >> 5;
#pragma unroll
        for (int i = 0; i < 4; ++i)
            t[ty + 8 * i][tx] = W[(size_t)(kb + ty + 8 * i) * HH + nb + tx];
        __syncthreads();
#pragma unroll
        for (int i = 0; i < 4; ++i)
            Hi[(size_t)(nb + ty + 8 * i) * HH + kb + tx] = __float2half(t[tx][ty + 8 * i]);
    }
}

// ================= single-pass fp16 HMMA GEMM + tanh + dot epilogue =================
// Merged launch: blockIdx.x < TXB -> text GEMM; else img GEMM.
// Epilogue reduces across the 4 warpn groups via smem -> ONE partial per 128-col block.
#define HMMA_SMEM (96 * 1024)

__device__ __forceinline__ void issue_chunk(
    const __half* __restrict__ Ap, const __half* __restrict__ Bp,
    int kt, uint32_t stageBase, int tid, int rowBase, int colBase) {
#pragma unroll
    for (int i = 0; i < 4; i++) {
        int u = tid + i * 256;
        cpa16(stageBase + SMEM_SWIZZLE_128B((uint32_t)u * 16u),
              Ap + (size_t)(rowBase + (u >> 3)) * HH + kt + (u & 7) * 8);
    }
#pragma unroll
    for (int i = 0; i < 4; i++) {
        int u = tid + i * 256;
        cpa16(stageBase + 16384u + SMEM_SWIZZLE_128B((uint32_t)u * 16u),
              Bp + (size_t)(colBase + (u >> 3)) * HH + kt + (u & 7) * 8);
    }
    asm volatile("cp.async.commit_group;");
}

__global__ __launch_bounds__(256, 2)
void hmma_tanh_dot(const __half* __restrict__ AT, const __half* __restrict__ AI,
                   const __half* __restrict__ WT, const __half* __restrict__ WI,
                   const float* __restrict__ avT, const float* __restrict__ avI,
                   float* __restrict__ outT, float* __restrict__ outI) {
    extern __shared__ __align__(1024) char smem[];
    const uint32_t sb = smem_u32(smem);
    const int tid = threadIdx.x;
    const int wid = tid >> 5, lane = tid & 31;
    const int warpm = wid & 1, warpn = wid >> 1;
    const int bx = blockIdx.x;
    const bool isT = bx < TXB;
    const __half* A = isT ? AT : AI;
    const __half* W = isT ? WT : WI;
    const float* av = isT ? avT : avI;
    float* outPart = isT ? outT : outI;
    const int nrows = isT ? MROWS_T : NROWS_I;
    const int rowBase = (isT ? bx : bx - TXB) * 128;
    const int colBase = blockIdx.y * 128;

    float acc[4][4][4];
#pragma unroll
    for (int i = 0; i < 4; i++)
#pragma unroll
        for (int j = 0; j < 4; j++)
#pragma unroll
            for (int q = 0; q < 4; q++) acc[i][j][q] = 0.f;

    issue_chunk(A, W, 0, sb, tid, rowBase, colBase);
    issue_chunk(A, W, 64, sb + 32768u, tid, rowBase, colBase);

    for (int it = 0; it < 12; ++it) {
        if (it < 11) asm volatile("cp.async.wait_group 1;");
        else         asm volatile("cp.async.wait_group 0;");
        __syncthreads();
        if (it < 10)
            issue_chunk(A, W, (it + 2) * 64, sb + (uint32_t)((it + 2) % 3) * 32768u,
                        tid, rowBase, colBase);

        const uint32_t abase = sb + (uint32_t)(it % 3) * 32768u;
        const uint32_t bbase = abase + 16384u;
#pragma unroll
        for (int ks = 0; ks < 4; ++ks) {
            uint32_t bf[2][4];
#pragma unroll
            for (int g = 0; g < 2; ++g) {
                const int n = warpn * 32 + g * 16 + (lane & 7) + ((lane >> 4) << 3);
                const int kb = ks * 32 + ((lane >> 3) & 1) * 16;
                ldmx4(bf[g], bbase + SMEM_SWIZZLE_128B((uint32_t)(n * 128 + kb)));
            }
#pragma unroll
            for (int mt = 0; mt < 4; ++mt) {
                uint32_t a[4];
                const int r = warpm * 64 + mt * 16 + (lane & 15);
                const int kb = ks * 32 + ((lane >> 4) << 4);
                ldmx4(a, abase + SMEM_SWIZZLE_128B((uint32_t)(r * 128 + kb)));
#pragma unroll
                for (int nt = 0; nt < 4; ++nt)
                    mma16816(acc[mt][nt], a, bf[nt >> 1][(nt & 1) * 2],
                             bf[nt >> 1][(nt & 1) * 2 + 1]);
            }
        }
    }

    // ---- epilogue: tanh * av per warp, then cross-warpn reduction via smem ----
    const float* avp = av + colBase + warpn * 32;
    float avv[4][2];
#pragma unroll
    for (int nt = 0; nt < 4; ++nt) {
        avv[nt][0] = avp[nt * 8 + (lane & 3) * 2];
        avv[nt][1] = avp[nt * 8 + (lane & 3) * 2 + 1];
    }
    float sarr[4][2];
#pragma unroll
    for (int mt = 0; mt < 4; ++mt) {
        float s0 = 0.f, s1 = 0.f;
#pragma unroll
        for (int nt = 0; nt < 4; ++nt) {
            s0 += fast_tanh(acc[mt][nt][0]) * avv[nt][0] + fast_tanh(acc[mt][nt][1]) * avv[nt][1];
            s1 += fast_tanh(acc[mt][nt][2]) * avv[nt][0] + fast_tanh(acc[mt][nt][3]) * avv[nt][1];
        }
        s0 += __shfl_xor_sync(0xffffffffu, s0, 1);
        s0 += __shfl_xor_sync(0xffffffffu, s0, 2);
        s1 += __shfl_xor_sync(0xffffffffu, s1, 1);
        s1 += __shfl_xor_sync(0xffffffffu, s1, 2);
        sarr[mt][0] = s0; sarr[mt][1] = s1;
    }
    __syncthreads();              // all warps done with mainloop smem reads
    float* rs = (float*)smem;     // [8 warps][64 local rows]
    if ((lane & 3) == 0) {
#pragma unroll
        for (int mt = 0; mt < 4; ++mt) {
            rs[wid * 64 + mt * 16 + (lane >> 2)] = sarr[mt][0];
            rs[wid * 64 + mt * 16 + 8 + (lane >> 2)] = sarr[mt][1];
        }
    }
    __syncthreads();
    if (wid < 4) {
        const int rl = wid * 32 + lane;      // local row 0..127
        const int wm = rl >> 6, idx = rl & 63;
        float sum = rs[(wm + 0) * 64 + idx] + rs[(wm + 2) * 64 + idx]
                  + rs[(wm + 4) * 64 + idx] + rs[(wm + 6) * 64 + idx];
        const int r = rowBase + rl;
        if (r < nrows) outPart[blockIdx.y * nrows + r] = sum;
    }
}

// ================= attend + in-block softmax: grid (B, 3, SCH), block 128 ==========
// Each thread owns S positions {tid, tid+128, tid+256, tid+384}; the block reduces
// the full-S softmax in-register (redundant across the 12 blocks per b; L2-hot),
// materializing only its own 128-entry chunk. sch==0 blocks also do the visual softmax.
__global__ __launch_bounds__(128)
void attend_part(const float* __restrict__ img) {
    __shared__ float red[128];
    __shared__ float wtc[128];
    __shared__ float wi[RR];
    const int b = blockIdx.x, tid = threadIdx.x;
    const int c = blockIdx.y * 128 + tid;     // half2/float2 column, 0..383
    const int sch = blockIdx.z;
    const int j0 = sch * 128;

    // textual softmax over S (each thread: 4 positions)
    float s[SCH];
#pragma unroll
    for (int i = 0; i < SCH; i++) {
        float v = 0.f;
#pragma unroll
        for (int p = 0; p < NPART; p++)
            v += g_ksc_part[p * MROWS_T + b * SS + i * 128 + tid];
        s[i] = v;
    }
    float lm = fmaxf(fmaxf(s[0], s[1]), fmaxf(s[2], s[3]));
    float mx = bmax(lm, red);
    float le = 0.f;
#pragma unroll
    for (int i = 0; i < SCH; i++) le += expf(s[i] - mx);
    float tot = bsum(le, red);
    wtc[tid] = expf(s[sch] - mx) / tot;

    // visual softmax over R (sch==0 blocks only)
    if (sch == 0) {
        float vs = 0.f, v0 = -1e30f;
        if (tid < RR) {
#pragma unroll
            for (int p = 0; p < NPART; p++) vs += g_isc_part[p * NROWS_I + b * RR + tid];
            v0 = vs;
        }
        float mv = bmax(v0, red);
        float ev = (tid < RR) ? expf(vs - mv) : 0.f;
        float tv = bsum(ev, red);
        if (tid < RR) wi[tid] = ev / tv;
    }
    __syncthreads();

    // att_text partial over this chunk's 128 S-rows
    {
        const __half2* tp = (const __half2*)g_tF + (size_t)(b * SS + j0) * (HH / 2) + c;
        float2 a = {0.f, 0.f};
#pragma unroll 8
        for (int j = 0; j < 128; ++j) {
            float2 v = __half22float2(tp[(size_t)j * (HH / 2)]);
            a.x += wtc[j] * v.x; a.y += wtc[j] * v.y;
        }
        ((float2*)(g_attTp + ((size_t)sch * BB + b) * HH))[c] = a;
    }
    // att_img (once per (b, colblock))
    if (sch == 0) {
        const float2* ip = (const float2*)(img + (size_t)b * RR * HH) + c;
        float2 a = {0.f, 0.f};
#pragma unroll
        for (int r = 0; r < RR; ++r) {
            float2 v = ip[(size_t)r * (HH / 2)];
            a.x += wi[r] * v.x; a.y += wi[r] * v.y;
        }
        ((float2*)(g_attI + b * HH))[c] = a;
    }
}

// ================= small GEMM: nI = tanh(attI@gi_w+b), nT = tanh(attT@gt_w+b) ======
__global__ __launch_bounds__(256)
void small_gemm_nit(const float* __restrict__ giw, const float* __restrict__ gib,
                    const float* __restrict__ gtw, const float* __restrict__ gtb) {
    const bool isT = blockIdx.y != 0;
    const float* W = isT ? gtw : giw;
    const float* bias = isT ? gtb : gib;
    float* C = isT ? g_nT : g_nI;

    __shared__ __align__(16) float As[32][36];
    __shared__ __align__(16) float Ws[32][128];
    const int tid = threadIdx.x;
    const int colBase = blockIdx.x * 128;
    const int tx = tid & 31;
    const int ty = tid >> 5;

    float acc[4][4];
#pragma unroll
    for (int i = 0; i < 4; i++)
#pragma unroll
        for (int j = 0; j < 4; j++) acc[i][j] = 0.f;

    for (int kt = 0; kt < HH; kt += 32) {
        {
            int r = tid >> 3;
            int kg = (tid & 7) << 2;
            float4 v;
            if (isT) {
                v = *(const float4*)(g_attTp + (size_t)r * HH + kt + kg);
#pragma unroll
                for (int s = 1; s < SCH; ++s) {
                    float4 p = *(const float4*)(g_attTp + ((size_t)s * BB + r) * HH + kt + kg);
                    v.x += p.x; v.y += p.y; v.z += p.z; v.w += p.w;
                }
            } else {
                v = *(const float4*)(g_attI + (size_t)r * HH + kt + kg);
            }
            As[kg + 0][r] = v.x; As[kg + 1][r] = v.y;
            As[kg + 2][r] = v.z; As[kg + 3][r] = v.w;
        }
#pragma unroll
        for (int i = 0; i < 4; i++) {
            int idx = tid + i * 256;
            int kk = idx >> 5;
            int ng = (idx & 31) << 2;
            *(float4*)&Ws[kk][ng] = *(const float4*)(W + (kt + kk) * HH + colBase + ng);
        }
        __syncthreads();
#pragma unroll
        for (int k = 0; k < 32; k++) {
            float4 av4 = *(const float4*)&As[k][ty * 4];
            float4 w = *(const float4*)&Ws[k][tx * 4];
            float a[4] = {av4.x, av4.y, av4.z, av4.w};
#pragma unroll
            for (int i = 0; i < 4; i++) {
                acc[i][0] = fmaf(a[i], w.x, acc[i][0]);
                acc[i][1] = fmaf(a[i], w.y, acc[i][1]);
                acc[i][2] = fmaf(a[i], w.z, acc[i][2]);
                acc[i][3] = fmaf(a[i], w.w, acc[i][3]);
            }
        }
        __syncthreads();
    }

    int col = colBase + tx * 4;
    float4 bv = *(const float4*)(bias + col);
#pragma unroll
    for (int i = 0; i < 4; i++) {
        int row = ty * 4 + i;
        float4 o;
        o.x = tanhf(acc[i][0] + bv.x);
        o.y = tanhf(acc[i][1] + bv.y);
        o.z = tanhf(acc[i][2] + bv.z);
        o.w = tanhf(acc[i][3] + bv.w);
        *(float4*)(C + row * HH + col) = o;
    }
}

// ================= small GEMM (generic): C[32,768] = tanh(A @ W + bias) ============
__global__ __launch_bounds__(256)
void small_gemm_tanh(const float* __restrict__ A, const float* __restrict__ W,
                     const float* __restrict__ bias, float* __restrict__ C) {
    __shared__ __align__(16) float As[32][36];
    __shared__ __align__(16) float Ws[32][128];
    const int tid = threadIdx.x;
    const int colBase = blockIdx.x * 128;
    const int tx = tid & 31;
    const int ty = tid >> 5;

    float acc[4][4];
#pragma unroll
    for (int i = 0; i < 4; i++)
#pragma unroll
        for (int j = 0; j < 4; j++) acc[i][j] = 0.f;

    for (int kt = 0; kt < HH; kt += 32) {
        {
            int r = tid >> 3;
            int kg = (tid & 7) << 2;
            float4 v = *(const float4*)(A + r * HH + kt + kg);
            As[kg + 0][r] = v.x; As[kg + 1][r] = v.y;
            As[kg + 2][r] = v.z; As[kg + 3][r] = v.w;
        }
#pragma unroll
        for (int i = 0; i < 4; i++) {
            int idx = tid + i * 256;
            int kk = idx >> 5;
            int ng = (idx & 31) << 2;
            *(float4*)&Ws[kk][ng] = *(const float4*)(W + (kt + kk) * HH + colBase + ng);
        }
        __syncthreads();
#pragma unroll
        for (int k = 0; k < 32; k++) {
            float4 av4 = *(const float4*)&As[k][ty * 4];
            float4 w = *(const float4*)&Ws[k][tx * 4];
            float a[4] = {av4.x, av4.y, av4.z, av4.w};
#pragma unroll
            for (int i = 0; i < 4; i++) {
                acc[i][0] = fmaf(a[i], w.x, acc[i][0]);
                acc[i][1] = fmaf(a[i], w.y, acc[i][1]);
                acc[i][2] = fmaf(a[i], w.z, acc[i][2]);
                acc[i][3] = fmaf(a[i], w.w, acc[i][3]);
            }
        }
        __syncthreads();
    }

    int col = colBase + tx * 4;
    float4 bv = *(const float4*)(bias + col);
#pragma unroll
    for (int i = 0; i < 4; i++) {
        int row = ty * 4 + i;
        float4 o;
        o.x = tanhf(acc[i][0] + bv.x);
        o.y = tanhf(acc[i][1] + bv.y);
        o.z = tanhf(acc[i][2] + bv.z);
        o.w = tanhf(acc[i][3] + bv.w);
        *(float4*)(C + row * HH + col) = o;
    }
}

// ================= gate + multimodal + fm score =================
__global__ void gate_mm_kernel(const float* __restrict__ ggw, const float* __restrict__ ggb,
                               const float* __restrict__ fgb) {
    __shared__ float red[256];
    const int b = blockIdx.x, tid = threadIdx.x;

    float gp = 0.f;
    for (int h = tid; h < HH; h += 256)
        gp += g_nI[b * HH + h] * ggw[h] + g_nT[b * HH + h] * ggw[HH + h];
    float gs = bsum(gp, red);
    float gate = 1.f / (1.f + expf(-(gs + ggb[0])));

    float fmp = 0.f;
    for (int h = tid; h < HH; h += 256) {
        float v = gate * g_nI[b * HH + h] + (1.f - gate) * g_nT[b * HH + h];
        g_mm[b * HH + h] = v;
        fmp += v * g_vfm[h];
    }
    float fsum = bsum(fmp, red);
    if (tid == 0) g_fmsc[b] = fsum + g_fmc + fgb[0];
}

// ================= output: warp per row, precomputed fdot, streaming stores ========
__global__ __launch_bounds__(256)
void out_kernel(float* __restrict__ out) {
    const int warp = threadIdx.x >> 5;
    const int lane = threadIdx.x & 31;
    const int row = blockIdx.x * 8 + warp;
    const int b = row >> 9;

    const float fg = 1.f / (1.f + expf(-(g_fdot[row] + g_fmsc[b])));
    const float4* fr = (const float4*)(g_frout + b * HH);
    float4* op = (float4*)(out + (size_t)row * HH);
#pragma unroll
    for (int i = 0; i < 6; i++) {
        float4 f = fr[lane + i * 32];
        float4 o;
        o.x = fg * f.x; o.y = fg * f.y; o.z = fg * f.z; o.w = fg * f.w;
        __stcs(op + lane + i * 32, o);     // write-once: evict-first
    }
}

// ================= launch =================
extern "C" void kernel_launch(void* const* d_in, const int* in_sizes, int n_in,
                              void* d_out, int out_size) {
    const float* text = (const float*)d_in[0];
    const float* img  = (const float*)d_in[1];
    const float* i1w  = (const float*)d_in[4];
    const float* a1w  = (const float*)d_in[5];
    const float* t2w  = (const float*)d_in[7];
    const float* a2w  = (const float*)d_in[10];
    const float* gtw  = (const float*)d_in[12];
    const float* gtb  = (const float*)d_in[13];
    const float* giw  = (const float*)d_in[14];
    const float* gib  = (const float*)d_in[15];
    const float* ggw  = (const float*)d_in[16];
    const float* ggb  = (const float*)d_in[17];
    const float* ftw  = (const float*)d_in[18];
    const float* fmw  = (const float*)d_in[19];
    const float* fmb  = (const float*)d_in[20];
    const float* fgw  = (const float*)d_in[21];
    const float* fgb  = (const float*)d_in[22];
    const float* frw  = (const float*)d_in[23];
    const float* frb  = (const float*)d_in[24];
    float* out = (float*)d_out;

    float* mm;    cudaGetSymbolAddress((void**)&mm,    g_mm);
    float* frout; cudaGetSymbolAddress((void**)&frout, g_frout);
    float* kscp;  cudaGetSymbolAddress((void**)&kscp,  g_ksc_part);
    float* iscp;  cudaGetSymbolAddress((void**)&iscp,  g_isc_part);
    __half *tF, *iF, *w2, *w1;
    cudaGetSymbolAddress((void**)&tF, g_tF);
    cudaGetSymbolAddress((void**)&iF, g_iF);
    cudaGetSymbolAddress((void**)&w2, g_w2);
    cudaGetSymbolAddress((void**)&w1, g_w1);

    cudaFuncSetAttribute(hmma_tanh_dot, cudaFuncAttributeMaxDynamicSharedMemorySize, HMMA_SMEM);

    // 1. rank-1 collapses (v_ft needed by cvt_prep text part)
    prep_kernel<<<HH, 128>>>(ftw, fmw, fmb, fgw);

    // 2. fp16 conversions + fgate dot + weight transposes (one launch)
    cvt_prep<<<2244 + 1152, 256>>>(text, img, t2w, i1w);

    // 3. merged text + img GEMM partials
    {
        dim3 g(TXB + MROWS_I / 128, HH / 128);
        hmma_tanh_dot<<<g, 256, HMMA_SMEM>>>(tF, iF, w2, w1, a2w + HH, a1w + HH, kscp, iscp);
    }

    // 4. attended-vector partials with in-block softmax (wide grid)
    {
        dim3 g(BB, 3, SCH);
        attend_part<<<g, 128>>>(img);
    }

    // 5. nI/nT small GEMMs (sums attT partials in the A loader)
    {
        dim3 g(NCB, 2);
        small_gemm_nit<<<g, 256>>>(giw, gib, gtw, gtb);
    }

    // 6. gate + multimodal + fm score
    gate_mm_kernel<<<BB, 256>>>(ggw, ggb, fgb);

    // 7. fr_out = tanh(mm @ fr_w + fr_b)
    small_gemm_tanh<<<NCB, 256>>>(mm, frw, frb, frout);

    // 8. output
    out_kernel<<<(BB * SS) / 8, 256>>>(out);
}